// round 1
// baseline (speedup 1.0000x reference)
#include <cuda_runtime.h>
#include <cstdint>
#include <cstddef>

// ---------------- problem constants (fixed shapes) ----------------
#define NN    8000      // nodes
#define EE    32000     // raw edges
#define ETOT  40000     // edges + self loops
#define GG    256       // graphs
#define FF    680       // in-features per head
#define HH    10        // heads
#define HFD   6800      // H*F
#define HF2   13600     // 2*HF

// ---------------- scratch (static device allocations) ----------------
__device__ float g_xh [(size_t)NN * HFD];   // x @ W_gat
__device__ float g_h  [(size_t)NN * HFD];   // GAT output (relu)
__device__ float g_xw [(size_t)NN * HFD];   // h @ W_gcn
__device__ float g_h2 [(size_t)NN * HFD];   // GCN output (relu)
__device__ float g_als[NN * HH];
__device__ float g_ald[NN * HH];
__device__ float g_e  [ETOT * HH];
__device__ float g_ex [ETOT * HH];
__device__ float g_m  [NN * HH];
__device__ float g_z  [NN * HH];
__device__ int   g_degI[NN];
__device__ float g_dinv[NN];
__device__ int   g_gstart[GG];
__device__ int   g_gend[GG];
__device__ int   g_gcnt[GG];
__device__ float g_pool[(size_t)GG * HF2];
__device__ float g_mlp1[GG * 512];
__device__ float g_mlp2[GG * 128];

// ---------------- helpers ----------------
__device__ __forceinline__ void atomicMaxF(float* addr, float val) {
    int old = __float_as_int(*addr);
    while (__int_as_float(old) < val) {
        int prev = atomicCAS((int*)addr, old, __float_as_int(val));
        if (prev == old) break;
        old = prev;
    }
}

// ---------------- generic tiled SGEMM:  C = A[M,K] @ B[K,N] (+bias)(+relu) ----------------
// Requires K % 8 == 0 and K % 4 == 0 (true for 680, 6800, 13600, 512, 128).
__global__ __launch_bounds__(256) void sgemm(const float* __restrict__ A,
                                             const float* __restrict__ B,
                                             const float* __restrict__ bias,
                                             float* __restrict__ C,
                                             int M, int N, int K,
                                             int hasBias, int doRelu) {
    __shared__ float As[8][128];
    __shared__ float Bs[8][128];
    const int tid   = threadIdx.x;
    const int tileM = blockIdx.y * 128;
    const int tileN = blockIdx.x * 128;

    const int aRow = tid >> 1;          // 0..127
    const int aK4  = (tid & 1) * 4;     // 0 or 4
    const int bRow = tid >> 5;          // 0..7
    const int bCol = (tid & 31) * 4;    // 0..124
    const int ty   = tid >> 4;          // 0..15
    const int tx   = tid & 15;          // 0..15

    float acc[8][8];
#pragma unroll
    for (int i = 0; i < 8; i++)
#pragma unroll
        for (int j = 0; j < 8; j++) acc[i][j] = 0.f;

    for (int k0 = 0; k0 < K; k0 += 8) {
        // load A tile (zero-fill rows past M)
        float4 av = make_float4(0.f, 0.f, 0.f, 0.f);
        int gr = tileM + aRow;
        if (gr < M) av = *reinterpret_cast<const float4*>(&A[(size_t)gr * K + k0 + aK4]);
        As[aK4 + 0][aRow] = av.x;
        As[aK4 + 1][aRow] = av.y;
        As[aK4 + 2][aRow] = av.z;
        As[aK4 + 3][aRow] = av.w;

        // load B tile (zero-fill cols past N)
        float4 bv = make_float4(0.f, 0.f, 0.f, 0.f);
        int gc = tileN + bCol;
        const float* bp = &B[(size_t)(k0 + bRow) * N + gc];
        if (gc + 3 < N) {
            bv = *reinterpret_cast<const float4*>(bp);
        } else {
            if (gc + 0 < N) bv.x = bp[0];
            if (gc + 1 < N) bv.y = bp[1];
            if (gc + 2 < N) bv.z = bp[2];
            if (gc + 3 < N) bv.w = bp[3];
        }
        *reinterpret_cast<float4*>(&Bs[bRow][bCol]) = bv;

        __syncthreads();
#pragma unroll
        for (int kk = 0; kk < 8; kk++) {
            float a[8], b[8];
            *reinterpret_cast<float4*>(&a[0]) = *reinterpret_cast<float4*>(&As[kk][ty * 8]);
            *reinterpret_cast<float4*>(&a[4]) = *reinterpret_cast<float4*>(&As[kk][ty * 8 + 4]);
            *reinterpret_cast<float4*>(&b[0]) = *reinterpret_cast<float4*>(&Bs[kk][tx * 8]);
            *reinterpret_cast<float4*>(&b[4]) = *reinterpret_cast<float4*>(&Bs[kk][tx * 8 + 4]);
#pragma unroll
            for (int i = 0; i < 8; i++)
#pragma unroll
                for (int j = 0; j < 8; j++) acc[i][j] = fmaf(a[i], b[j], acc[i][j]);
        }
        __syncthreads();
    }

#pragma unroll
    for (int i = 0; i < 8; i++) {
        int row = tileM + ty * 8 + i;
        if (row >= M) continue;
#pragma unroll
        for (int j = 0; j < 8; j++) {
            int col = tileN + tx * 8 + j;
            if (col < N) {
                float v = acc[i][j];
                if (hasBias) v += bias[col];
                if (doRelu) v = fmaxf(v, 0.f);
                C[(size_t)row * N + col] = v;
            }
        }
    }
}

// ---------------- misc kernels ----------------
__global__ void k_init() {
    int i = blockIdx.x * blockDim.x + threadIdx.x;
    if (i < NN * HH) { g_m[i] = -3.0e38f; g_z[i] = 0.f; }
    if (i < NN)      { g_degI[i] = 0; }
    if (i < GG)      { g_gstart[i] = 0x7fffffff; g_gend[i] = -1; g_gcnt[i] = 0; }
}

__global__ void k_fill_bias(float* __restrict__ dst, const float* __restrict__ bias,
                            size_t total, int cols) {
    size_t i = (size_t)blockIdx.x * blockDim.x + threadIdx.x;
    if (i < total) dst[i] = bias[i % cols];
}

// per-node, per-head attention logits: al = <xh[n, h, :], a[h, :]>
__global__ void k_attn(const float* __restrict__ xh, const float* __restrict__ a_s,
                       const float* __restrict__ a_d) {
    int n = blockIdx.x;
    int w = threadIdx.x >> 5;
    int lane = threadIdx.x & 31;
    if (w >= HH) return;
    const float* row = xh + (size_t)n * HFD + w * FF;
    const float* as  = a_s + w * FF;
    const float* ad  = a_d + w * FF;
    float s1 = 0.f, s2 = 0.f;
    for (int f = lane; f < FF; f += 32) {
        float v = row[f];
        s1 = fmaf(v, as[f], s1);
        s2 = fmaf(v, ad[f], s2);
    }
#pragma unroll
    for (int o = 16; o; o >>= 1) {
        s1 += __shfl_down_sync(0xffffffffu, s1, o);
        s2 += __shfl_down_sync(0xffffffffu, s2, o);
    }
    if (lane == 0) { g_als[n * HH + w] = s1; g_ald[n * HH + w] = s2; }
}

__global__ void k_edge1(const int* __restrict__ ei) {
    int k = blockIdx.x * blockDim.x + threadIdx.x;
    if (k >= ETOT) return;
    int src = (k < EE) ? ei[k]      : (k - EE);
    int dst = (k < EE) ? ei[EE + k] : (k - EE);
    atomicAdd(&g_degI[dst], 1);
#pragma unroll
    for (int h = 0; h < HH; h++) {
        float v = g_als[src * HH + h] + g_ald[dst * HH + h];
        float e = fmaxf(v, 0.2f * v);   // leaky_relu(0.2)
        g_e[k * HH + h] = e;
        atomicMaxF(&g_m[dst * HH + h], e);
    }
}

__global__ void k_edge2(const int* __restrict__ ei) {
    int k = blockIdx.x * blockDim.x + threadIdx.x;
    if (k >= ETOT) return;
    int dst = (k < EE) ? ei[EE + k] : (k - EE);
#pragma unroll
    for (int h = 0; h < HH; h++) {
        float ex = expf(g_e[k * HH + h] - g_m[dst * HH + h]);
        g_ex[k * HH + h] = ex;
        atomicAdd(&g_z[dst * HH + h], ex);
    }
}

__global__ __launch_bounds__(256) void k_gat_agg(const int* __restrict__ ei) {
    int k = blockIdx.x;
    int src = (k < EE) ? ei[k]      : (k - EE);
    int dst = (k < EE) ? ei[EE + k] : (k - EE);
    __shared__ float sa[HH];
    if (threadIdx.x < HH)
        sa[threadIdx.x] = g_ex[k * HH + threadIdx.x] / (g_z[dst * HH + threadIdx.x] + 1e-16f);
    __syncthreads();
    const float* xr = g_xh + (size_t)src * HFD;
    float* orow = g_h + (size_t)dst * HFD;
    for (int f = threadIdx.x; f < HFD; f += 256) {
        int h = f / FF;
        atomicAdd(&orow[f], sa[h] * xr[f]);
    }
}

__global__ void k_relu(float* __restrict__ a, size_t n) {
    size_t i = (size_t)blockIdx.x * blockDim.x + threadIdx.x;
    if (i < n) a[i] = fmaxf(a[i], 0.f);
}

__global__ void k_dinv() {
    int i = blockIdx.x * blockDim.x + threadIdx.x;
    if (i < NN) g_dinv[i] = 1.0f / sqrtf((float)g_degI[i]);
}

__global__ __launch_bounds__(256) void k_gcn_agg(const int* __restrict__ ei) {
    int k = blockIdx.x;
    int src = (k < EE) ? ei[k]      : (k - EE);
    int dst = (k < EE) ? ei[EE + k] : (k - EE);
    float coef = g_dinv[src] * g_dinv[dst];
    const float* xr = g_xw + (size_t)src * HFD;
    float* orow = g_h2 + (size_t)dst * HFD;
    for (int f = threadIdx.x; f < HFD; f += 256)
        atomicAdd(&orow[f], coef * xr[f]);
}

__global__ void k_ranges(const int* __restrict__ batch) {
    int i = blockIdx.x * blockDim.x + threadIdx.x;
    if (i >= NN) return;
    int b = batch[i];
    if (b >= 0 && b < GG) {
        atomicMin(&g_gstart[b], i);
        atomicMax(&g_gend[b], i);
        atomicAdd(&g_gcnt[b], 1);
    }
}

__global__ __launch_bounds__(256) void k_pool() {
    int g = blockIdx.y;
    int f = blockIdx.x * blockDim.x + threadIdx.x;
    if (f >= HFD) return;
    int s = g_gstart[g], e = g_gend[g];
    float mx = -3.0e38f, sm = 0.f;
    for (int n = s; n <= e; n++) {
        float v = g_h2[(size_t)n * HFD + f];
        mx = fmaxf(mx, v);
        sm += v;
    }
    g_pool[(size_t)g * HF2 + f]       = mx;
    g_pool[(size_t)g * HF2 + HFD + f] = sm / (float)g_gcnt[g];
}

// ---------------- launch ----------------
extern "C" void kernel_launch(void* const* d_in, const int* in_sizes, int n_in,
                              void* d_out, int out_size) {
    const float* x     = (const float*)d_in[0];
    const int*   ei    = (const int*)  d_in[1];
    const int*   batch = (const int*)  d_in[2];
    const float* W_gat = (const float*)d_in[3];
    const float* a_src = (const float*)d_in[4];
    const float* a_dst = (const float*)d_in[5];
    const float* b_gat = (const float*)d_in[6];
    const float* W_gcn = (const float*)d_in[7];
    const float* b_gcn = (const float*)d_in[8];
    const float* W1    = (const float*)d_in[9];
    const float* b1    = (const float*)d_in[10];
    const float* W2    = (const float*)d_in[11];
    const float* b2    = (const float*)d_in[12];
    const float* W3    = (const float*)d_in[13];
    const float* b3    = (const float*)d_in[14];
    float* out = (float*)d_out;

    float *p_xh, *p_h, *p_xw, *p_h2, *p_pool, *p_m1, *p_m2;
    cudaGetSymbolAddress((void**)&p_xh,   g_xh);
    cudaGetSymbolAddress((void**)&p_h,    g_h);
    cudaGetSymbolAddress((void**)&p_xw,   g_xw);
    cudaGetSymbolAddress((void**)&p_h2,   g_h2);
    cudaGetSymbolAddress((void**)&p_pool, g_pool);
    cudaGetSymbolAddress((void**)&p_m1,   g_mlp1);
    cudaGetSymbolAddress((void**)&p_m2,   g_mlp2);

    const size_t NHF = (size_t)NN * HFD;
    const int ew = (NN * HH + 255) / 256;
    const int nb_nhf = (int)((NHF + 255) / 256);

    // init
    k_init<<<ew, 256>>>();
    k_fill_bias<<<nb_nhf, 256>>>(p_h,  b_gat, NHF, HFD);
    k_fill_bias<<<nb_nhf, 256>>>(p_h2, b_gcn, NHF, HFD);

    // GAT: xh = x @ W_gat
    {
        dim3 grid((HFD + 127) / 128, (NN + 127) / 128);
        sgemm<<<grid, 256>>>(x, W_gat, nullptr, p_xh, NN, HFD, FF, 0, 0);
    }
    k_attn<<<NN, 320>>>(p_xh, a_src, a_dst);
    k_edge1<<<(ETOT + 255) / 256, 256>>>(ei);
    k_edge2<<<(ETOT + 255) / 256, 256>>>(ei);
    k_gat_agg<<<ETOT, 256>>>(ei);
    k_relu<<<nb_nhf, 256>>>(p_h, NHF);

    // GCN
    k_dinv<<<(NN + 255) / 256, 256>>>();
    {
        dim3 grid((HFD + 127) / 128, (NN + 127) / 128);
        sgemm<<<grid, 256>>>(p_h, W_gcn, nullptr, p_xw, NN, HFD, HFD, 0, 0);
    }
    k_gcn_agg<<<ETOT, 256>>>(ei);
    k_relu<<<nb_nhf, 256>>>(p_h2, NHF);

    // pooling
    k_ranges<<<(NN + 255) / 256, 256>>>(batch);
    {
        dim3 grid((HFD + 255) / 256, GG);
        k_pool<<<grid, 256>>>();
    }

    // MLP
    {
        dim3 grid((512 + 127) / 128, (GG + 127) / 128);
        sgemm<<<grid, 256>>>(p_pool, W1, b1, p_m1, GG, 512, HF2, 1, 1);
    }
    {
        dim3 grid((128 + 127) / 128, (GG + 127) / 128);
        sgemm<<<grid, 256>>>(p_m1, W2, b2, p_m2, GG, 128, 512, 1, 0);
    }
    {
        dim3 grid((64 + 127) / 128, (GG + 127) / 128);
        sgemm<<<grid, 256>>>(p_m2, W3, b3, out, GG, 64, 128, 1, 0);
    }
}

// round 3
// speedup vs baseline: 2.1599x; 2.1599x over previous
#include <cuda_runtime.h>
#include <cuda_bf16.h>
#include <cstdint>
#include <cstddef>

// ---------------- problem constants (fixed shapes) ----------------
#define NN    8000      // nodes
#define EE    32000     // raw edges
#define ETOT  40000     // edges + self loops
#define GG    256       // graphs
#define FF    680       // in-features per head
#define HH    10        // heads
#define HFD   6800      // H*F
#define HF2   13600     // 2*HF

// padded dims for tensor-core GEMMs
#define MP_G  8064      // 63*128  (rows of node matrices)
#define KP1   704       // GEMM1 K (680 padded to 32-mult)
#define KP2   6848      // GEMM2 K (6800 padded)
#define KPM   13632     // MLP1 K (13600 padded)
#define NPAD  6912      // 54*128  (N=6800 padded)

// ---------------- scratch (static device allocations) ----------------
__device__ float g_xh [(size_t)NN * HFD];
__device__ float g_h  [(size_t)NN * HFD];
__device__ float g_xw [(size_t)NN * HFD];
__device__ float g_h2 [(size_t)NN * HFD];
__device__ float g_als[NN * HH];
__device__ float g_ald[NN * HH];
__device__ float g_e  [ETOT * HH];
__device__ float g_ex [ETOT * HH];
__device__ float g_m  [NN * HH];
__device__ float g_z  [NN * HH];
__device__ int   g_degI[NN];
__device__ float g_dinv[NN];
__device__ int   g_gstart[GG];
__device__ int   g_gend[GG];
__device__ int   g_gcnt[GG];
__device__ float g_pool[(size_t)GG * HF2];
__device__ float g_mlp1[GG * 512];
__device__ float g_mlp2[GG * 128];

// bf16 3-term split panels: A2=[Ahi|Alo|Ahi], B2t=[Bhi|Bhi|Blo] along K'
__device__ __nv_bfloat16 s_a2[(size_t)MP_G * (3 * KP2)];   // covers all three GEMMs
__device__ __nv_bfloat16 s_b2[(size_t)NPAD * (3 * KP2)];

// ---------------- PTX helpers ----------------
__device__ __forceinline__ uint32_t smem_u32(const void* p) {
    uint32_t a;
    asm("{ .reg .u64 t; cvta.to.shared.u64 t, %1; cvt.u32.u64 %0, t; }" : "=r"(a) : "l"(p));
    return a;
}

__device__ __forceinline__ void cp16(uint32_t dst, const void* src) {
    asm volatile("cp.async.cg.shared.global [%0], [%1], 16;" :: "r"(dst), "l"(src));
}
#define CP_COMMIT() asm volatile("cp.async.commit_group;" ::: "memory")
__device__ __forceinline__ void cp_wait(int pend) {
    if (pend <= 0)      asm volatile("cp.async.wait_group 0;" ::: "memory");
    else if (pend == 1) asm volatile("cp.async.wait_group 1;" ::: "memory");
    else                asm volatile("cp.async.wait_group 2;" ::: "memory");
}

__device__ __forceinline__ void ldsm4(uint32_t* r, uint32_t addr) {
    asm volatile("ldmatrix.sync.aligned.m8n8.x4.shared.b16 {%0,%1,%2,%3}, [%4];"
                 : "=r"(r[0]), "=r"(r[1]), "=r"(r[2]), "=r"(r[3]) : "r"(addr));
}

__device__ __forceinline__ void mma16816(float* d, const uint32_t* a, uint32_t b0, uint32_t b1) {
    asm volatile("mma.sync.aligned.m16n8k16.row.col.f32.bf16.bf16.f32 "
                 "{%0,%1,%2,%3}, {%4,%5,%6,%7}, {%8,%9}, {%0,%1,%2,%3};"
                 : "+f"(d[0]), "+f"(d[1]), "+f"(d[2]), "+f"(d[3])
                 : "r"(a[0]), "r"(a[1]), "r"(a[2]), "r"(a[3]), "r"(b0), "r"(b1));
}

// smem tile addressing: 128 rows x 32 bf16 (64B/row), 16B chunks XOR-swizzled
__device__ __forceinline__ uint32_t sm_tile_off(int row, int chunk) {
    return (uint32_t)(row * 64 + ((chunk ^ ((row >> 1) & 3)) << 4));
}

// ---------------- mma.sync bf16 GEMM: C[M,N] = A2[M,K2] @ B2t[N,K2]^T ----------------
#define BM 128
#define BN 128
#define BK 32
#define STG 4
#define STAGE_BYTES 16384          // A: 128*64B = 8192, B: 8192
#define SMEM_MMA (STG * STAGE_BYTES)

__global__ __launch_bounds__(256, 1) void mma_gemm(
    const __nv_bfloat16* __restrict__ A2, const __nv_bfloat16* __restrict__ B2,
    const float* __restrict__ bias, float* __restrict__ C,
    int M, int N, int ldc, int K2, int tiles_m, int tiles_n, int flags)
{
    extern __shared__ char smem[];
    uint32_t sb = smem_u32(smem);
    const int tid = threadIdx.x;
    const int wid = tid >> 5;
    const int lane = tid & 31;
    const int warp_m = wid & 3;     // 4 warps along M
    const int warp_n = wid >> 2;    // 2 warps along N

    // block swizzle (GROUP_M = 8) for L2 reuse
    int gm, gn;
    {
        const int GM = 8;
        int bid = blockIdx.x;
        int per = GM * tiles_n;
        int grp = bid / per;
        int fm  = grp * GM;
        int gsz = tiles_m - fm; if (gsz > GM) gsz = GM;
        int r = bid - grp * per;
        gm = fm + r % gsz;
        gn = r / gsz;
    }

    const int CH = K2 / BK;

    // per-thread cp.async coords: row = tid/2, two 16B chunks
    const int lrow = tid >> 1;
    const int lc0  = (tid & 1) * 2;
    const char* gA = (const char*)(A2 + (size_t)(gm * BM + lrow) * K2);
    const char* gB = (const char*)(B2 + (size_t)(gn * BN + lrow) * K2);
    uint32_t sAoff0 = sm_tile_off(lrow, lc0);
    uint32_t sAoff1 = sm_tile_off(lrow, lc0 + 1);

    // ldmatrix addresses (offsets within a stage), per ks
    uint32_t aoff[2][2], boff[4][2];
#pragma unroll
    for (int ks = 0; ks < 2; ks++) {
        int chunk = ks * 2 + (lane >> 4);
#pragma unroll
        for (int mi = 0; mi < 2; mi++)
            aoff[mi][ks] = sm_tile_off(warp_m * 32 + mi * 16 + (lane & 15), chunk);
#pragma unroll
        for (int g = 0; g < 4; g++)
            boff[g][ks] = 8192 + sm_tile_off(warp_n * 64 + g * 16 + (lane & 15), chunk);
    }

    float acc[2][8][4];
#pragma unroll
    for (int mi = 0; mi < 2; mi++)
#pragma unroll
        for (int ni = 0; ni < 8; ni++)
#pragma unroll
            for (int j = 0; j < 4; j++) acc[mi][ni][j] = 0.f;

    // prologue: preload 3 stages
#pragma unroll
    for (int c = 0; c < 3; c++) {
        uint32_t stb = sb + c * STAGE_BYTES;
        long off0 = (long)(c * BK + lc0 * 8) * 2;
        cp16(stb + sAoff0, gA + off0);
        cp16(stb + sAoff1, gA + off0 + 16);
        cp16(stb + 8192 + sAoff0, gB + off0);
        cp16(stb + 8192 + sAoff1, gB + off0 + 16);
        CP_COMMIT();
    }

    for (int c = 0; c < CH; c++) {
        int pend = CH - 1 - c; if (pend > 2) pend = 2;
        cp_wait(pend);
        __syncthreads();

        uint32_t stb = sb + (c & (STG - 1)) * STAGE_BYTES;
#pragma unroll
        for (int ks = 0; ks < 2; ks++) {
            uint32_t a[2][4], b[4][4];
            ldsm4(a[0], stb + aoff[0][ks]);
            ldsm4(a[1], stb + aoff[1][ks]);
#pragma unroll
            for (int g = 0; g < 4; g++) ldsm4(b[g], stb + boff[g][ks]);
#pragma unroll
            for (int mi = 0; mi < 2; mi++)
#pragma unroll
                for (int ni = 0; ni < 8; ni++) {
                    int g = ni >> 1, h = ni & 1;
                    mma16816(acc[mi][ni], a[mi], b[g][h], b[g][h + 2]);
                }
        }

        if (c + 3 < CH) {
            uint32_t dtb = sb + ((c + 3) & (STG - 1)) * STAGE_BYTES;
            long off0 = (long)((c + 3) * BK + lc0 * 8) * 2;
            cp16(dtb + sAoff0, gA + off0);
            cp16(dtb + sAoff1, gA + off0 + 16);
            cp16(dtb + 8192 + sAoff0, gB + off0);
            cp16(dtb + 8192 + sAoff1, gB + off0 + 16);
            CP_COMMIT();
        }
    }

    // epilogue
    int row0 = gm * BM + warp_m * 32 + (lane >> 2);
    int col0 = gn * BN + warp_n * 64 + (lane & 3) * 2;
#pragma unroll
    for (int mi = 0; mi < 2; mi++) {
#pragma unroll
        for (int ni = 0; ni < 8; ni++) {
            int r = row0 + mi * 16;
            int cc = col0 + ni * 8;
#pragma unroll
            for (int half = 0; half < 2; half++) {
                int rr = r + half * 8;
                if (rr < M) {
                    float v0 = acc[mi][ni][half * 2 + 0];
                    float v1 = acc[mi][ni][half * 2 + 1];
                    if (cc < N) {
                        float v = v0;
                        if (flags & 1) v += bias[cc];
                        if (flags & 2) v = fmaxf(v, 0.f);
                        C[(size_t)rr * ldc + cc] = v;
                    }
                    if (cc + 1 < N) {
                        float v = v1;
                        if (flags & 1) v += bias[cc + 1];
                        if (flags & 2) v = fmaxf(v, 0.f);
                        C[(size_t)rr * ldc + cc + 1] = v;
                    }
                }
            }
        }
    }
}

// ---------------- conversion kernels ----------------
// A2[m, kk] over K2=3*KP: seg0=hi, seg1=lo, seg2=hi  (pads -> 0)
__global__ void k_splitA2(const float* __restrict__ src, __nv_bfloat16* __restrict__ dst,
                          int M, int K, int KP)
{
    int kk = blockIdx.x * 256 + threadIdx.x;
    int m = blockIdx.y;
    int K2 = 3 * KP;
    if (kk >= K2) return;
    int seg = kk / KP;
    int k = kk - seg * KP;
    float v = (m < M && k < K) ? src[(size_t)m * K + k] : 0.f;
    __nv_bfloat16 h = __float2bfloat16(v);
    __nv_bfloat16 o = (seg == 1) ? __float2bfloat16(v - __bfloat162float(h)) : h;
    dst[(size_t)m * K2 + kk] = o;
}

// B2t[n, kk]: transpose of B[K,N]; seg0=hi, seg1=hi, seg2=lo (pads -> 0)
__global__ void k_splitBT2(const float* __restrict__ src, __nv_bfloat16* __restrict__ dst,
                           int K, int N, int KP)
{
    __shared__ float t[32][33];
    int k0 = blockIdx.x * 32, n0 = blockIdx.y * 32;
    int tx = threadIdx.x, ty = threadIdx.y;   // 32 x 8
    size_t K2 = 3 * (size_t)KP;
#pragma unroll
    for (int j = ty; j < 32; j += 8) {
        int k = k0 + j, n = n0 + tx;
        t[j][tx] = (k < K && n < N) ? src[(size_t)k * N + n] : 0.f;
    }
    __syncthreads();
#pragma unroll
    for (int j = ty; j < 32; j += 8) {
        int n = n0 + j, k = k0 + tx;
        float v = t[tx][j];
        __nv_bfloat16 h = __float2bfloat16(v);
        __nv_bfloat16 l = __float2bfloat16(v - __bfloat162float(h));
        size_t base = (size_t)n * K2 + k;
        dst[base] = h;
        dst[base + KP] = h;
        dst[base + 2 * KP] = l;
    }
}

// ---------------- scalar SGEMM (tiny MLP tail layers) ----------------
__global__ __launch_bounds__(256) void sgemm(const float* __restrict__ A,
                                             const float* __restrict__ B,
                                             const float* __restrict__ bias,
                                             float* __restrict__ C,
                                             int M, int N, int K,
                                             int hasBias, int doRelu) {
    __shared__ float As[8][128];
    __shared__ float Bs[8][128];
    const int tid   = threadIdx.x;
    const int tileM = blockIdx.y * 128;
    const int tileN = blockIdx.x * 128;

    const int aRow = tid >> 1;
    const int aK4  = (tid & 1) * 4;
    const int bRow = tid >> 5;
    const int bCol = (tid & 31) * 4;
    const int ty   = tid >> 4;
    const int tx   = tid & 15;

    float acc[8][8];
#pragma unroll
    for (int i = 0; i < 8; i++)
#pragma unroll
        for (int j = 0; j < 8; j++) acc[i][j] = 0.f;

    for (int k0 = 0; k0 < K; k0 += 8) {
        float4 av = make_float4(0.f, 0.f, 0.f, 0.f);
        int gr = tileM + aRow;
        if (gr < M) av = *reinterpret_cast<const float4*>(&A[(size_t)gr * K + k0 + aK4]);
        As[aK4 + 0][aRow] = av.x;
        As[aK4 + 1][aRow] = av.y;
        As[aK4 + 2][aRow] = av.z;
        As[aK4 + 3][aRow] = av.w;

        float4 bv = make_float4(0.f, 0.f, 0.f, 0.f);
        int gc = tileN + bCol;
        const float* bp = &B[(size_t)(k0 + bRow) * N + gc];
        if (gc + 3 < N) {
            bv = *reinterpret_cast<const float4*>(bp);
        } else {
            if (gc + 0 < N) bv.x = bp[0];
            if (gc + 1 < N) bv.y = bp[1];
            if (gc + 2 < N) bv.z = bp[2];
            if (gc + 3 < N) bv.w = bp[3];
        }
        *reinterpret_cast<float4*>(&Bs[bRow][bCol]) = bv;

        __syncthreads();
#pragma unroll
        for (int kk = 0; kk < 8; kk++) {
            float a[8], b[8];
            *reinterpret_cast<float4*>(&a[0]) = *reinterpret_cast<float4*>(&As[kk][ty * 8]);
            *reinterpret_cast<float4*>(&a[4]) = *reinterpret_cast<float4*>(&As[kk][ty * 8 + 4]);
            *reinterpret_cast<float4*>(&b[0]) = *reinterpret_cast<float4*>(&Bs[kk][tx * 8]);
            *reinterpret_cast<float4*>(&b[4]) = *reinterpret_cast<float4*>(&Bs[kk][tx * 8 + 4]);
#pragma unroll
            for (int i = 0; i < 8; i++)
#pragma unroll
                for (int j = 0; j < 8; j++) acc[i][j] = fmaf(a[i], b[j], acc[i][j]);
        }
        __syncthreads();
    }

#pragma unroll
    for (int i = 0; i < 8; i++) {
        int row = tileM + ty * 8 + i;
        if (row >= M) continue;
#pragma unroll
        for (int j = 0; j < 8; j++) {
            int col = tileN + tx * 8 + j;
            if (col < N) {
                float v = acc[i][j];
                if (hasBias) v += bias[col];
                if (doRelu) v = fmaxf(v, 0.f);
                C[(size_t)row * N + col] = v;
            }
        }
    }
}

// ---------------- misc kernels (unchanged, verified pipeline) ----------------
__device__ __forceinline__ void atomicMaxF(float* addr, float val) {
    int old = __float_as_int(*addr);
    while (__int_as_float(old) < val) {
        int prev = atomicCAS((int*)addr, old, __float_as_int(val));
        if (prev == old) break;
        old = prev;
    }
}

__global__ void k_init() {
    int i = blockIdx.x * blockDim.x + threadIdx.x;
    if (i < NN * HH) { g_m[i] = -3.0e38f; g_z[i] = 0.f; }
    if (i < NN)      { g_degI[i] = 0; }
    if (i < GG)      { g_gstart[i] = 0x7fffffff; g_gend[i] = -1; g_gcnt[i] = 0; }
}

__global__ void k_fill_bias(float* __restrict__ dst, const float* __restrict__ bias,
                            size_t total, int cols) {
    size_t i = (size_t)blockIdx.x * blockDim.x + threadIdx.x;
    if (i < total) dst[i] = bias[i % cols];
}

__global__ void k_attn(const float* __restrict__ xh, const float* __restrict__ a_s,
                       const float* __restrict__ a_d) {
    int n = blockIdx.x;
    int w = threadIdx.x >> 5;
    int lane = threadIdx.x & 31;
    if (w >= HH) return;
    const float* row = xh + (size_t)n * HFD + w * FF;
    const float* as  = a_s + w * FF;
    const float* ad  = a_d + w * FF;
    float s1 = 0.f, s2 = 0.f;
    for (int f = lane; f < FF; f += 32) {
        float v = row[f];
        s1 = fmaf(v, as[f], s1);
        s2 = fmaf(v, ad[f], s2);
    }
#pragma unroll
    for (int o = 16; o; o >>= 1) {
        s1 += __shfl_down_sync(0xffffffffu, s1, o);
        s2 += __shfl_down_sync(0xffffffffu, s2, o);
    }
    if (lane == 0) { g_als[n * HH + w] = s1; g_ald[n * HH + w] = s2; }
}

__global__ void k_edge1(const int* __restrict__ ei) {
    int k = blockIdx.x * blockDim.x + threadIdx.x;
    if (k >= ETOT) return;
    int src = (k < EE) ? ei[k]      : (k - EE);
    int dst = (k < EE) ? ei[EE + k] : (k - EE);
    atomicAdd(&g_degI[dst], 1);
#pragma unroll
    for (int h = 0; h < HH; h++) {
        float v = g_als[src * HH + h] + g_ald[dst * HH + h];
        float e = fmaxf(v, 0.2f * v);
        g_e[k * HH + h] = e;
        atomicMaxF(&g_m[dst * HH + h], e);
    }
}

__global__ void k_edge2(const int* __restrict__ ei) {
    int k = blockIdx.x * blockDim.x + threadIdx.x;
    if (k >= ETOT) return;
    int dst = (k < EE) ? ei[EE + k] : (k - EE);
#pragma unroll
    for (int h = 0; h < HH; h++) {
        float ex = expf(g_e[k * HH + h] - g_m[dst * HH + h]);
        g_ex[k * HH + h] = ex;
        atomicAdd(&g_z[dst * HH + h], ex);
    }
}

__global__ __launch_bounds__(256) void k_gat_agg(const int* __restrict__ ei) {
    int k = blockIdx.x;
    int src = (k < EE) ? ei[k]      : (k - EE);
    int dst = (k < EE) ? ei[EE + k] : (k - EE);
    __shared__ float sa[HH];
    if (threadIdx.x < HH)
        sa[threadIdx.x] = g_ex[k * HH + threadIdx.x] / (g_z[dst * HH + threadIdx.x] + 1e-16f);
    __syncthreads();
    const float* xr = g_xh + (size_t)src * HFD;
    float* orow = g_h + (size_t)dst * HFD;
    for (int f = threadIdx.x; f < HFD; f += 256) {
        int h = f / FF;
        atomicAdd(&orow[f], sa[h] * xr[f]);
    }
}

__global__ void k_relu(float* __restrict__ a, size_t n) {
    size_t i = (size_t)blockIdx.x * blockDim.x + threadIdx.x;
    if (i < n) a[i] = fmaxf(a[i], 0.f);
}

__global__ void k_dinv() {
    int i = blockIdx.x * blockDim.x + threadIdx.x;
    if (i < NN) g_dinv[i] = 1.0f / sqrtf((float)g_degI[i]);
}

__global__ __launch_bounds__(256) void k_gcn_agg(const int* __restrict__ ei) {
    int k = blockIdx.x;
    int src = (k < EE) ? ei[k]      : (k - EE);
    int dst = (k < EE) ? ei[EE + k] : (k - EE);
    float coef = g_dinv[src] * g_dinv[dst];
    const float* xr = g_xw + (size_t)src * HFD;
    float* orow = g_h2 + (size_t)dst * HFD;
    for (int f = threadIdx.x; f < HFD; f += 256)
        atomicAdd(&orow[f], coef * xr[f]);
}

__global__ void k_ranges(const int* __restrict__ batch) {
    int i = blockIdx.x * blockDim.x + threadIdx.x;
    if (i >= NN) return;
    int b = batch[i];
    if (b >= 0 && b < GG) {
        atomicMin(&g_gstart[b], i);
        atomicMax(&g_gend[b], i);
        atomicAdd(&g_gcnt[b], 1);
    }
}

__global__ __launch_bounds__(256) void k_pool() {
    int g = blockIdx.y;
    int f = blockIdx.x * blockDim.x + threadIdx.x;
    if (f >= HFD) return;
    int s = g_gstart[g], e = g_gend[g];
    float mx = -3.0e38f, sm = 0.f;
    for (int n = s; n <= e; n++) {
        float v = g_h2[(size_t)n * HFD + f];
        mx = fmaxf(mx, v);
        sm += v;
    }
    g_pool[(size_t)g * HF2 + f]       = mx;
    g_pool[(size_t)g * HF2 + HFD + f] = sm / (float)g_gcnt[g];
}

// ---------------- launch ----------------
extern "C" void kernel_launch(void* const* d_in, const int* in_sizes, int n_in,
                              void* d_out, int out_size) {
    const float* x     = (const float*)d_in[0];
    const int*   ei    = (const int*)  d_in[1];
    const int*   batch = (const int*)  d_in[2];
    const float* W_gat = (const float*)d_in[3];
    const float* a_src = (const float*)d_in[4];
    const float* a_dst = (const float*)d_in[5];
    const float* b_gat = (const float*)d_in[6];
    const float* W_gcn = (const float*)d_in[7];
    const float* b_gcn = (const float*)d_in[8];
    const float* W1    = (const float*)d_in[9];
    const float* b1    = (const float*)d_in[10];
    const float* W2    = (const float*)d_in[11];
    const float* b2    = (const float*)d_in[12];
    const float* W3    = (const float*)d_in[13];
    const float* b3    = (const float*)d_in[14];
    float* out = (float*)d_out;

    float *p_xh, *p_h, *p_xw, *p_h2, *p_pool, *p_m1, *p_m2;
    __nv_bfloat16 *p_a2, *p_b2;
    cudaGetSymbolAddress((void**)&p_xh,   g_xh);
    cudaGetSymbolAddress((void**)&p_h,    g_h);
    cudaGetSymbolAddress((void**)&p_xw,   g_xw);
    cudaGetSymbolAddress((void**)&p_h2,   g_h2);
    cudaGetSymbolAddress((void**)&p_pool, g_pool);
    cudaGetSymbolAddress((void**)&p_m1,   g_mlp1);
    cudaGetSymbolAddress((void**)&p_m2,   g_mlp2);
    cudaGetSymbolAddress((void**)&p_a2,   s_a2);
    cudaGetSymbolAddress((void**)&p_b2,   s_b2);

    cudaFuncSetAttribute(mma_gemm, cudaFuncAttributeMaxDynamicSharedMemorySize, SMEM_MMA);

    const size_t NHF = (size_t)NN * HFD;
    const int ew = (NN * HH + 255) / 256;
    const int nb_nhf = (int)((NHF + 255) / 256);

    // init
    k_init<<<ew, 256>>>();
    k_fill_bias<<<nb_nhf, 256>>>(p_h,  b_gat, NHF, HFD);
    k_fill_bias<<<nb_nhf, 256>>>(p_h2, b_gcn, NHF, HFD);

    const int TM = MP_G / 128;   // 63
    const int TN = NPAD / 128;   // 54

    // ---- GEMM1: xh = x @ W_gat ----
    {
        const int K2 = 3 * KP1;   // 2112
        dim3 gA((K2 + 255) / 256, MP_G);
        k_splitA2<<<gA, 256>>>(x, p_a2, NN, FF, KP1);
        dim3 gB(KP1 / 32, NPAD / 32);
        k_splitBT2<<<gB, dim3(32, 8)>>>(W_gat, p_b2, FF, HFD, KP1);
        mma_gemm<<<TM * TN, 256, SMEM_MMA>>>(p_a2, p_b2, nullptr, p_xh,
                                             NN, HFD, HFD, K2, TM, TN, 0);
    }

    k_attn<<<NN, 320>>>(p_xh, a_src, a_dst);
    k_edge1<<<(ETOT + 255) / 256, 256>>>(ei);
    k_edge2<<<(ETOT + 255) / 256, 256>>>(ei);
    k_gat_agg<<<ETOT, 256>>>(ei);
    k_relu<<<nb_nhf, 256>>>(p_h, NHF);

    // GCN
    k_dinv<<<(NN + 255) / 256, 256>>>();

    // ---- GEMM2: xw = h @ W_gcn ----
    {
        const int K2 = 3 * KP2;   // 20544
        dim3 gA((K2 + 255) / 256, MP_G);
        k_splitA2<<<gA, 256>>>(p_h, p_a2, NN, HFD, KP2);
        dim3 gB(KP2 / 32, NPAD / 32);
        k_splitBT2<<<gB, dim3(32, 8)>>>(W_gcn, p_b2, HFD, HFD, KP2);
        mma_gemm<<<TM * TN, 256, SMEM_MMA>>>(p_a2, p_b2, nullptr, p_xw,
                                             NN, HFD, HFD, K2, TM, TN, 0);
    }

    k_gcn_agg<<<ETOT, 256>>>(ei);
    k_relu<<<nb_nhf, 256>>>(p_h2, NHF);

    // pooling
    k_ranges<<<(NN + 255) / 256, 256>>>(batch);
    {
        dim3 grid((HFD + 255) / 256, GG);
        k_pool<<<grid, 256>>>();
    }

    // ---- MLP1: relu(pool @ W1 + b1) ----
    {
        const int K2 = 3 * KPM;   // 40896
        dim3 gA((K2 + 255) / 256, GG);
        k_splitA2<<<gA, 256>>>(p_pool, p_a2, GG, HF2, KPM);
        dim3 gB(KPM / 32, 512 / 32);
        k_splitBT2<<<gB, dim3(32, 8)>>>(W1, p_b2, HF2, 512, KPM);
        mma_gemm<<<2 * 4, 256, SMEM_MMA>>>(p_a2, p_b2, b1, p_m1,
                                           GG, 512, 512, K2, 2, 4, 3);
    }

    // MLP tail (tiny)
    {
        dim3 grid(1, 2);
        sgemm<<<grid, 256>>>(p_m1, W2, b2, p_m2, GG, 128, 512, 1, 0);
    }
    {
        dim3 grid(1, 2);
        sgemm<<<grid, 256>>>(p_m2, W3, b3, out, GG, 64, 128, 1, 0);
    }
}

// round 4
// speedup vs baseline: 2.5001x; 1.1575x over previous
#include <cuda_runtime.h>
#include <cuda_bf16.h>
#include <cstdint>
#include <cstddef>

// ---------------- problem constants (fixed shapes) ----------------
#define NN    8000      // nodes
#define EE    32000     // raw edges
#define ETOT  40000     // edges + self loops
#define GG    256       // graphs
#define FF    680       // in-features per head
#define HH    10        // heads
#define HFD   6800      // H*F
#define HF2   13600     // 2*HF

// padded dims for tensor-core GEMMs
#define MP_G  8064      // 63*128  (rows of node matrices)
#define KP1   704       // GEMM1 K (680 padded to 64-mult)
#define KP2   6848      // GEMM2 K (6800 padded)
#define KPM   13632     // MLP1 K (13600 padded)
#define NPAD  6912      // 54*128  (N=6800 padded)

#define FCH   27        // ceil(HFD/256)

// ---------------- scratch (static device allocations) ----------------
__device__ float g_xh [(size_t)NN * HFD];
__device__ float g_h  [(size_t)NN * HFD];
__device__ float g_xw [(size_t)NN * HFD];
__device__ float g_h2 [(size_t)NN * HFD];
__device__ float g_als[NN * HH];
__device__ float g_ald[NN * HH];
__device__ float g_alpha[(size_t)ETOT * HH];
__device__ int   g_cnt[NN];
__device__ int   g_cur[NN];
__device__ int   g_start[NN + 1];
__device__ int   g_esrc[ETOT];
__device__ float g_dinv[NN];
__device__ int   g_pstart[GG];
__device__ int   g_pend[GG];
__device__ int   g_pcnt[GG];
__device__ float g_pool[(size_t)GG * HF2];
__device__ float g_mlp1[GG * 512];
__device__ float g_mlp2[GG * 128];

// bf16 split panels: A=[hi|lo], Bt=[hi|lo] along K (each segment KP wide)
__device__ __nv_bfloat16 s_a2[(size_t)MP_G * (2 * KP2)];
__device__ __nv_bfloat16 s_b2[(size_t)NPAD * (2 * KP2)];

// ---------------- PTX helpers ----------------
__device__ __forceinline__ uint32_t smem_u32(const void* p) {
    uint32_t a;
    asm("{ .reg .u64 t; cvta.to.shared.u64 t, %1; cvt.u32.u64 %0, t; }" : "=r"(a) : "l"(p));
    return a;
}

__device__ __forceinline__ void cp16(uint32_t dst, const void* src) {
    asm volatile("cp.async.cg.shared.global [%0], [%1], 16;" :: "r"(dst), "l"(src));
}
#define CP_COMMIT() asm volatile("cp.async.commit_group;" ::: "memory")
__device__ __forceinline__ void cp_wait(int pend) {
    if (pend <= 0)      asm volatile("cp.async.wait_group 0;" ::: "memory");
    else if (pend == 1) asm volatile("cp.async.wait_group 1;" ::: "memory");
    else                asm volatile("cp.async.wait_group 2;" ::: "memory");
}

__device__ __forceinline__ void ldsm4(uint32_t* r, uint32_t addr) {
    asm volatile("ldmatrix.sync.aligned.m8n8.x4.shared.b16 {%0,%1,%2,%3}, [%4];"
                 : "=r"(r[0]), "=r"(r[1]), "=r"(r[2]), "=r"(r[3]) : "r"(addr));
}

__device__ __forceinline__ void mma16816(float* d, const uint32_t* a, uint32_t b0, uint32_t b1) {
    asm volatile("mma.sync.aligned.m16n8k16.row.col.f32.bf16.bf16.f32 "
                 "{%0,%1,%2,%3}, {%4,%5,%6,%7}, {%8,%9}, {%0,%1,%2,%3};"
                 : "+f"(d[0]), "+f"(d[1]), "+f"(d[2]), "+f"(d[3])
                 : "r"(a[0]), "r"(a[1]), "r"(a[2]), "r"(a[3]), "r"(b0), "r"(b1));
}

// smem tile addressing: 128 rows x 32 bf16 (64B/row), 16B chunks XOR-swizzled
__device__ __forceinline__ uint32_t sm_tile_off(int row, int chunk) {
    return (uint32_t)(row * 64 + ((chunk ^ ((row >> 1) & 3)) << 4));
}

// chunk c (0..3*CH0) -> source k-chunks in the [hi|lo] panels
__device__ __forceinline__ void chunk_map(int c, int CH0, int& kA, int& kB) {
    int seg = (c >= 2 * CH0) ? 2 : ((c >= CH0) ? 1 : 0);
    int r = c - seg * CH0;
    kA = r + ((seg == 1) ? CH0 : 0);   // seg1: A-lo
    kB = r + ((seg == 2) ? CH0 : 0);   // seg2: B-lo
}

// ---------------- mma.sync bf16 GEMM: C = A2[M,2KP] (x) B2t[N,2KP], 3 split terms ----------------
#define BM 128
#define BN 128
#define BK 32
#define STG 4
#define STAGE_BYTES 16384
#define SMEM_MMA (STG * STAGE_BYTES)

__global__ __launch_bounds__(256, 1) void mma_gemm(
    const __nv_bfloat16* __restrict__ A2, const __nv_bfloat16* __restrict__ B2,
    const float* __restrict__ bias, float* __restrict__ C,
    int M, int N, int ldc, int KP, int tiles_m, int tiles_n, int flags)
{
    extern __shared__ char smem[];
    uint32_t sb = smem_u32(smem);
    const int tid = threadIdx.x;
    const int wid = tid >> 5;
    const int lane = tid & 31;
    const int warp_m = wid & 3;
    const int warp_n = wid >> 2;

    int gm, gn;
    {
        const int GM = 8;
        int bid = blockIdx.x;
        int per = GM * tiles_n;
        int grp = bid / per;
        int fm  = grp * GM;
        int gsz = tiles_m - fm; if (gsz > GM) gsz = GM;
        int r = bid - grp * per;
        gm = fm + r % gsz;
        gn = r / gsz;
    }

    const int CH0 = KP / BK;
    const int CH = 3 * CH0;
    const int KA2 = 2 * KP;

    const int lrow = tid >> 1;
    const int lc0  = (tid & 1) * 2;
    const char* gA = (const char*)(A2 + (size_t)(gm * BM + lrow) * KA2);
    const char* gB = (const char*)(B2 + (size_t)(gn * BN + lrow) * KA2);
    uint32_t sAoff0 = sm_tile_off(lrow, lc0);
    uint32_t sAoff1 = sm_tile_off(lrow, lc0 + 1);

    uint32_t aoff[2][2], boff[4][2];
#pragma unroll
    for (int ks = 0; ks < 2; ks++) {
        int chunk = ks * 2 + (lane >> 4);
#pragma unroll
        for (int mi = 0; mi < 2; mi++)
            aoff[mi][ks] = sm_tile_off(warp_m * 32 + mi * 16 + (lane & 15), chunk);
#pragma unroll
        for (int g = 0; g < 4; g++)
            boff[g][ks] = 8192 + sm_tile_off(warp_n * 64 + g * 16 + (lane & 15), chunk);
    }

    float acc[2][8][4];
#pragma unroll
    for (int mi = 0; mi < 2; mi++)
#pragma unroll
        for (int ni = 0; ni < 8; ni++)
#pragma unroll
            for (int j = 0; j < 4; j++) acc[mi][ni][j] = 0.f;

    // prologue: preload 3 stages
#pragma unroll
    for (int c = 0; c < 3; c++) {
        int kA, kB; chunk_map(c, CH0, kA, kB);
        uint32_t stb = sb + c * STAGE_BYTES;
        long offA = (long)(kA * BK + lc0 * 8) * 2;
        long offB = (long)(kB * BK + lc0 * 8) * 2;
        cp16(stb + sAoff0, gA + offA);
        cp16(stb + sAoff1, gA + offA + 16);
        cp16(stb + 8192 + sAoff0, gB + offB);
        cp16(stb + 8192 + sAoff1, gB + offB + 16);
        CP_COMMIT();
    }

    for (int c = 0; c < CH; c++) {
        int pend = CH - 1 - c; if (pend > 2) pend = 2;
        cp_wait(pend);
        __syncthreads();

        uint32_t stb = sb + (c & (STG - 1)) * STAGE_BYTES;
#pragma unroll
        for (int ks = 0; ks < 2; ks++) {
            uint32_t a[2][4], b[4][4];
            ldsm4(a[0], stb + aoff[0][ks]);
            ldsm4(a[1], stb + aoff[1][ks]);
#pragma unroll
            for (int g = 0; g < 4; g++) ldsm4(b[g], stb + boff[g][ks]);
#pragma unroll
            for (int mi = 0; mi < 2; mi++)
#pragma unroll
                for (int ni = 0; ni < 8; ni++) {
                    int g = ni >> 1, h = ni & 1;
                    mma16816(acc[mi][ni], a[mi], b[g][h], b[g][h + 2]);
                }
        }

        if (c + 3 < CH) {
            int kA, kB; chunk_map(c + 3, CH0, kA, kB);
            uint32_t dtb = sb + ((c + 3) & (STG - 1)) * STAGE_BYTES;
            long offA = (long)(kA * BK + lc0 * 8) * 2;
            long offB = (long)(kB * BK + lc0 * 8) * 2;
            cp16(dtb + sAoff0, gA + offA);
            cp16(dtb + sAoff1, gA + offA + 16);
            cp16(dtb + 8192 + sAoff0, gB + offB);
            cp16(dtb + 8192 + sAoff1, gB + offB + 16);
            CP_COMMIT();
        }
    }

    // epilogue
    int row0 = gm * BM + warp_m * 32 + (lane >> 2);
    int col0 = gn * BN + warp_n * 64 + (lane & 3) * 2;
#pragma unroll
    for (int mi = 0; mi < 2; mi++) {
#pragma unroll
        for (int ni = 0; ni < 8; ni++) {
            int r = row0 + mi * 16;
            int cc = col0 + ni * 8;
#pragma unroll
            for (int half = 0; half < 2; half++) {
                int rr = r + half * 8;
                if (rr < M) {
                    float v0 = acc[mi][ni][half * 2 + 0];
                    float v1 = acc[mi][ni][half * 2 + 1];
                    if (cc < N) {
                        float v = v0;
                        if (flags & 1) v += bias[cc];
                        if (flags & 2) v = fmaxf(v, 0.f);
                        C[(size_t)rr * ldc + cc] = v;
                    }
                    if (cc + 1 < N) {
                        float v = v1;
                        if (flags & 1) v += bias[cc + 1];
                        if (flags & 2) v = fmaxf(v, 0.f);
                        C[(size_t)rr * ldc + cc + 1] = v;
                    }
                }
            }
        }
    }
}

// ---------------- conversion kernels (vectorized, deduped) ----------------
// A[M,K] fp32 -> dst[Mp, 2KP] bf16: [hi | lo]; pads -> 0.  1 thread = 4 elems.
__global__ void k_splitA2(const float* __restrict__ src, __nv_bfloat16* __restrict__ dst,
                          int M, int K, int KP)
{
    int k = (blockIdx.x * 256 + threadIdx.x) * 4;
    int m = blockIdx.y;
    if (k >= KP) return;
    float4 v = make_float4(0.f, 0.f, 0.f, 0.f);
    if (m < M && k < K) v = *reinterpret_cast<const float4*>(&src[(size_t)m * K + k]);
    __nv_bfloat16 h0 = __float2bfloat16(v.x), h1 = __float2bfloat16(v.y);
    __nv_bfloat16 h2 = __float2bfloat16(v.z), h3 = __float2bfloat16(v.w);
    __nv_bfloat16 l0 = __float2bfloat16(v.x - __bfloat162float(h0));
    __nv_bfloat16 l1 = __float2bfloat16(v.y - __bfloat162float(h1));
    __nv_bfloat16 l2 = __float2bfloat16(v.z - __bfloat162float(h2));
    __nv_bfloat16 l3 = __float2bfloat16(v.w - __bfloat162float(h3));
    uint2 hp, lp;
    hp.x = ((uint32_t)__bfloat16_as_ushort(h1) << 16) | __bfloat16_as_ushort(h0);
    hp.y = ((uint32_t)__bfloat16_as_ushort(h3) << 16) | __bfloat16_as_ushort(h2);
    lp.x = ((uint32_t)__bfloat16_as_ushort(l1) << 16) | __bfloat16_as_ushort(l0);
    lp.y = ((uint32_t)__bfloat16_as_ushort(l3) << 16) | __bfloat16_as_ushort(l2);
    size_t base = (size_t)m * (2 * KP);
    *reinterpret_cast<uint2*>(&dst[base + k]) = hp;
    *reinterpret_cast<uint2*>(&dst[base + KP + k]) = lp;
}

// B[K,N] fp32 -> transposed dst[Np, 2KP] bf16: [hi | lo]; pads -> 0.
__global__ void k_splitBT2(const float* __restrict__ src, __nv_bfloat16* __restrict__ dst,
                           int K, int N, int KP)
{
    __shared__ float t[64][33];
    int k0 = blockIdx.x * 64, n0 = blockIdx.y * 32;
    int tx = threadIdx.x, ty = threadIdx.y;   // 32 x 8
#pragma unroll
    for (int it = 0; it < 8; it++) {
        int k = k0 + ty + it * 8;
        int n = n0 + tx;
        t[ty + it * 8][tx] = (k < K && n < N) ? src[(size_t)k * N + n] : 0.f;
    }
    __syncthreads();
    int uid = ty * 32 + tx;
    int nl = uid >> 3;            // 0..31
    int kg = (uid & 7) * 8;       // 0,8,...,56
    size_t base = (size_t)(n0 + nl) * (2 * KP) + k0;
#pragma unroll
    for (int q = 0; q < 4; q++) {
        int kk = kg + q * 2;
        float v0 = t[kk][nl], v1 = t[kk + 1][nl];
        __nv_bfloat16 h0 = __float2bfloat16(v0), h1 = __float2bfloat16(v1);
        __nv_bfloat16 l0 = __float2bfloat16(v0 - __bfloat162float(h0));
        __nv_bfloat16 l1 = __float2bfloat16(v1 - __bfloat162float(h1));
        uint32_t hp = ((uint32_t)__bfloat16_as_ushort(h1) << 16) | __bfloat16_as_ushort(h0);
        uint32_t lp = ((uint32_t)__bfloat16_as_ushort(l1) << 16) | __bfloat16_as_ushort(l0);
        *reinterpret_cast<uint32_t*>(&dst[base + kk]) = hp;
        *reinterpret_cast<uint32_t*>(&dst[base + KP + kk]) = lp;
    }
}

// ---------------- scalar SGEMM (tiny MLP tail layers) ----------------
__global__ __launch_bounds__(256) void sgemm(const float* __restrict__ A,
                                             const float* __restrict__ B,
                                             const float* __restrict__ bias,
                                             float* __restrict__ C,
                                             int M, int N, int K,
                                             int hasBias, int doRelu) {
    __shared__ float As[8][128];
    __shared__ float Bs[8][128];
    const int tid   = threadIdx.x;
    const int tileM = blockIdx.y * 128;
    const int tileN = blockIdx.x * 128;

    const int aRow = tid >> 1;
    const int aK4  = (tid & 1) * 4;
    const int bRow = tid >> 5;
    const int bCol = (tid & 31) * 4;
    const int ty   = tid >> 4;
    const int tx   = tid & 15;

    float acc[8][8];
#pragma unroll
    for (int i = 0; i < 8; i++)
#pragma unroll
        for (int j = 0; j < 8; j++) acc[i][j] = 0.f;

    for (int k0 = 0; k0 < K; k0 += 8) {
        float4 av = make_float4(0.f, 0.f, 0.f, 0.f);
        int gr = tileM + aRow;
        if (gr < M) av = *reinterpret_cast<const float4*>(&A[(size_t)gr * K + k0 + aK4]);
        As[aK4 + 0][aRow] = av.x;
        As[aK4 + 1][aRow] = av.y;
        As[aK4 + 2][aRow] = av.z;
        As[aK4 + 3][aRow] = av.w;

        float4 bv = make_float4(0.f, 0.f, 0.f, 0.f);
        int gc = tileN + bCol;
        const float* bp = &B[(size_t)(k0 + bRow) * N + gc];
        if (gc + 3 < N) {
            bv = *reinterpret_cast<const float4*>(bp);
        } else {
            if (gc + 0 < N) bv.x = bp[0];
            if (gc + 1 < N) bv.y = bp[1];
            if (gc + 2 < N) bv.z = bp[2];
            if (gc + 3 < N) bv.w = bp[3];
        }
        *reinterpret_cast<float4*>(&Bs[bRow][bCol]) = bv;

        __syncthreads();
#pragma unroll
        for (int kk = 0; kk < 8; kk++) {
            float a[8], b[8];
            *reinterpret_cast<float4*>(&a[0]) = *reinterpret_cast<float4*>(&As[kk][ty * 8]);
            *reinterpret_cast<float4*>(&a[4]) = *reinterpret_cast<float4*>(&As[kk][ty * 8 + 4]);
            *reinterpret_cast<float4*>(&b[0]) = *reinterpret_cast<float4*>(&Bs[kk][tx * 8]);
            *reinterpret_cast<float4*>(&b[4]) = *reinterpret_cast<float4*>(&Bs[kk][tx * 8 + 4]);
#pragma unroll
            for (int i = 0; i < 8; i++)
#pragma unroll
                for (int j = 0; j < 8; j++) acc[i][j] = fmaf(a[i], b[j], acc[i][j]);
        }
        __syncthreads();
    }

#pragma unroll
    for (int i = 0; i < 8; i++) {
        int row = tileM + ty * 8 + i;
        if (row >= M) continue;
#pragma unroll
        for (int j = 0; j < 8; j++) {
            int col = tileN + tx * 8 + j;
            if (col < N) {
                float v = acc[i][j];
                if (hasBias) v += bias[col];
                if (doRelu) v = fmaxf(v, 0.f);
                C[(size_t)row * N + col] = v;
            }
        }
    }
}

// ---------------- CSR build ----------------
__global__ void k_init() {
    int i = blockIdx.x * blockDim.x + threadIdx.x;
    if (i < NN) { g_cnt[i] = 0; g_cur[i] = 0; }
    if (i < GG) { g_pstart[i] = 0x7fffffff; g_pend[i] = -1; g_pcnt[i] = 0; }
}

__global__ void k_count(const int* __restrict__ ei) {
    int k = blockIdx.x * blockDim.x + threadIdx.x;
    if (k >= ETOT) return;
    int dst = (k < EE) ? ei[EE + k] : (k - EE);
    atomicAdd(&g_cnt[dst], 1);
}

__global__ __launch_bounds__(1024) void k_scan() {
    __shared__ int sd[1024];
    __shared__ int scarry;
    int tid = threadIdx.x;
    if (tid == 0) { scarry = 0; g_start[0] = 0; }
    __syncthreads();
    for (int base = 0; base < NN; base += 1024) {
        int v = (base + tid < NN) ? g_cnt[base + tid] : 0;
        sd[tid] = v;
        __syncthreads();
        for (int o = 1; o < 1024; o <<= 1) {
            int t = (tid >= o) ? sd[tid - o] : 0;
            __syncthreads();
            sd[tid] += t;
            __syncthreads();
        }
        int run = scarry;
        if (base + tid < NN) g_start[base + tid + 1] = run + sd[tid];
        __syncthreads();
        if (tid == 1023) scarry = run + sd[1023];
        __syncthreads();
    }
}

__global__ void k_scatter(const int* __restrict__ ei) {
    int k = blockIdx.x * blockDim.x + threadIdx.x;
    if (k >= ETOT) return;
    int src = (k < EE) ? ei[k]      : (k - EE);
    int dst = (k < EE) ? ei[EE + k] : (k - EE);
    int pos = g_start[dst] + atomicAdd(&g_cur[dst], 1);
    g_esrc[pos] = src;
}

__global__ void k_dinv() {
    int i = blockIdx.x * blockDim.x + threadIdx.x;
    if (i < NN) g_dinv[i] = rsqrtf((float)g_cnt[i]);
}

// ---------------- attention ----------------
__global__ void k_attn(const float* __restrict__ xh, const float* __restrict__ a_s,
                       const float* __restrict__ a_d) {
    int n = blockIdx.x;
    int w = threadIdx.x >> 5;
    int lane = threadIdx.x & 31;
    if (w >= HH) return;
    const float* row = xh + (size_t)n * HFD + w * FF;
    const float* as  = a_s + w * FF;
    const float* ad  = a_d + w * FF;
    float s1 = 0.f, s2 = 0.f;
    for (int f = lane; f < FF; f += 32) {
        float v = row[f];
        s1 = fmaf(v, as[f], s1);
        s2 = fmaf(v, ad[f], s2);
    }
#pragma unroll
    for (int o = 16; o; o >>= 1) {
        s1 += __shfl_down_sync(0xffffffffu, s1, o);
        s2 += __shfl_down_sync(0xffffffffu, s2, o);
    }
    if (lane == 0) { g_als[n * HH + w] = s1; g_ald[n * HH + w] = s2; }
}

// per-node segment softmax over CSR edges; warp per node, lane = head
__global__ void k_softmax() {
    int node = blockIdx.x * blockDim.y + threadIdx.y;
    if (node >= NN) return;
    int lane = threadIdx.x;
    bool act = lane < HH;
    int s = g_start[node], e = g_start[node + 1];
    float ald_v = act ? g_ald[node * HH + lane] : 0.f;
    float mx = -3.0e38f;
    for (int p = s; p < e; p++) {
        int src = g_esrc[p];
        if (act) {
            float v = g_als[src * HH + lane] + ald_v;
            v = fmaxf(v, 0.2f * v);
            mx = fmaxf(mx, v);
        }
    }
    float z = 0.f;
    for (int p = s; p < e; p++) {
        int src = g_esrc[p];
        if (act) {
            float v = g_als[src * HH + lane] + ald_v;
            v = fmaxf(v, 0.2f * v);
            float ex = expf(v - mx);
            g_alpha[(size_t)p * HH + lane] = ex;
            z += ex;
        }
    }
    float inv = 1.f / (z + 1e-16f);
    for (int p = s; p < e; p++)
        if (act) g_alpha[(size_t)p * HH + lane] *= inv;
}

// ---------------- aggregation (CSR, no atomics, bias+relu fused) ----------------
__global__ __launch_bounds__(256) void k_gat_agg(const float* __restrict__ bias) {
    int n = blockIdx.x, tid = threadIdx.x;
    int s = g_start[n], e = g_start[n + 1];
    int hh[FCH];
    float acc[FCH];
#pragma unroll
    for (int i = 0; i < FCH; i++) {
        int f = tid + i * 256;
        hh[i] = f / FF;
        acc[i] = (f < HFD) ? bias[f] : 0.f;
    }
    for (int p = s; p < e; p++) {
        int src = g_esrc[p];
        const float* xr = g_xh + (size_t)src * HFD;
        const float* al = g_alpha + (size_t)p * HH;
#pragma unroll
        for (int i = 0; i < FCH; i++) {
            int f = tid + i * 256;
            if (f < HFD) acc[i] = fmaf(al[hh[i]], xr[f], acc[i]);
        }
    }
    float* o = g_h + (size_t)n * HFD;
#pragma unroll
    for (int i = 0; i < FCH; i++) {
        int f = tid + i * 256;
        if (f < HFD) o[f] = fmaxf(acc[i], 0.f);
    }
}

__global__ __launch_bounds__(256) void k_gcn_agg(const float* __restrict__ bias) {
    int n = blockIdx.x, tid = threadIdx.x;
    int s = g_start[n], e = g_start[n + 1];
    float dv = g_dinv[n];
    float acc[FCH];
#pragma unroll
    for (int i = 0; i < FCH; i++) {
        int f = tid + i * 256;
        acc[i] = (f < HFD) ? bias[f] : 0.f;
    }
    for (int p = s; p < e; p++) {
        int src = g_esrc[p];
        float coef = g_dinv[src] * dv;
        const float* xr = g_xw + (size_t)src * HFD;
#pragma unroll
        for (int i = 0; i < FCH; i++) {
            int f = tid + i * 256;
            if (f < HFD) acc[i] = fmaf(coef, xr[f], acc[i]);
        }
    }
    float* o = g_h2 + (size_t)n * HFD;
#pragma unroll
    for (int i = 0; i < FCH; i++) {
        int f = tid + i * 256;
        if (f < HFD) o[f] = fmaxf(acc[i], 0.f);
    }
}

// ---------------- pooling ----------------
__global__ void k_ranges(const int* __restrict__ batch) {
    int i = blockIdx.x * blockDim.x + threadIdx.x;
    if (i >= NN) return;
    int b = batch[i];
    if (b >= 0 && b < GG) {
        atomicMin(&g_pstart[b], i);
        atomicMax(&g_pend[b], i);
        atomicAdd(&g_pcnt[b], 1);
    }
}

__global__ __launch_bounds__(256) void k_pool() {
    int g = blockIdx.y;
    int f = blockIdx.x * blockDim.x + threadIdx.x;
    if (f >= HFD) return;
    int s = g_pstart[g], e = g_pend[g];
    float mx = -3.0e38f, sm = 0.f;
    for (int n = s; n <= e; n++) {
        float v = g_h2[(size_t)n * HFD + f];
        mx = fmaxf(mx, v);
        sm += v;
    }
    g_pool[(size_t)g * HF2 + f]       = mx;
    g_pool[(size_t)g * HF2 + HFD + f] = sm / (float)g_pcnt[g];
}

// ---------------- launch ----------------
extern "C" void kernel_launch(void* const* d_in, const int* in_sizes, int n_in,
                              void* d_out, int out_size) {
    const float* x     = (const float*)d_in[0];
    const int*   ei    = (const int*)  d_in[1];
    const int*   batch = (const int*)  d_in[2];
    const float* W_gat = (const float*)d_in[3];
    const float* a_src = (const float*)d_in[4];
    const float* a_dst = (const float*)d_in[5];
    const float* b_gat = (const float*)d_in[6];
    const float* W_gcn = (const float*)d_in[7];
    const float* b_gcn = (const float*)d_in[8];
    const float* W1    = (const float*)d_in[9];
    const float* b1    = (const float*)d_in[10];
    const float* W2    = (const float*)d_in[11];
    const float* b2    = (const float*)d_in[12];
    const float* W3    = (const float*)d_in[13];
    const float* b3    = (const float*)d_in[14];
    float* out = (float*)d_out;

    float *p_xh, *p_h, *p_xw, *p_h2, *p_pool, *p_m1, *p_m2;
    __nv_bfloat16 *p_a2, *p_b2;
    cudaGetSymbolAddress((void**)&p_xh,   g_xh);
    cudaGetSymbolAddress((void**)&p_h,    g_h);
    cudaGetSymbolAddress((void**)&p_xw,   g_xw);
    cudaGetSymbolAddress((void**)&p_h2,   g_h2);
    cudaGetSymbolAddress((void**)&p_pool, g_pool);
    cudaGetSymbolAddress((void**)&p_m1,   g_mlp1);
    cudaGetSymbolAddress((void**)&p_m2,   g_mlp2);
    cudaGetSymbolAddress((void**)&p_a2,   s_a2);
    cudaGetSymbolAddress((void**)&p_b2,   s_b2);

    cudaFuncSetAttribute(mma_gemm, cudaFuncAttributeMaxDynamicSharedMemorySize, SMEM_MMA);

    const int TM = MP_G / 128;   // 63
    const int TN = NPAD / 128;   // 54

    // CSR build + degrees
    k_init<<<(NN + 255) / 256, 256>>>();
    k_count<<<(ETOT + 255) / 256, 256>>>(ei);
    k_scan<<<1, 1024>>>();
    k_scatter<<<(ETOT + 255) / 256, 256>>>(ei);
    k_dinv<<<(NN + 255) / 256, 256>>>();

    // ---- GEMM1: xh = x @ W_gat ----
    {
        dim3 gA((KP1 / 4 + 255) / 256, MP_G);
        k_splitA2<<<gA, 256>>>(x, p_a2, NN, FF, KP1);
        dim3 gB(KP1 / 64, NPAD / 32);
        k_splitBT2<<<gB, dim3(32, 8)>>>(W_gat, p_b2, FF, HFD, KP1);
        mma_gemm<<<TM * TN, 256, SMEM_MMA>>>(p_a2, p_b2, nullptr, p_xh,
                                             NN, HFD, HFD, KP1, TM, TN, 0);
    }

    k_attn<<<NN, 320>>>(p_xh, a_src, a_dst);
    k_softmax<<<(NN + 7) / 8, dim3(32, 8)>>>();
    k_gat_agg<<<NN, 256>>>(b_gat);

    // ---- GEMM2: xw = h @ W_gcn ----
    {
        dim3 gA((KP2 / 4 + 255) / 256, MP_G);
        k_splitA2<<<gA, 256>>>(p_h, p_a2, NN, HFD, KP2);
        dim3 gB(KP2 / 64, NPAD / 32);
        k_splitBT2<<<gB, dim3(32, 8)>>>(W_gcn, p_b2, HFD, HFD, KP2);
        mma_gemm<<<TM * TN, 256, SMEM_MMA>>>(p_a2, p_b2, nullptr, p_xw,
                                             NN, HFD, HFD, KP2, TM, TN, 0);
    }

    k_gcn_agg<<<NN, 256>>>(b_gcn);

    // pooling
    k_ranges<<<(NN + 255) / 256, 256>>>(batch);
    {
        dim3 grid((HFD + 255) / 256, GG);
        k_pool<<<grid, 256>>>();
    }

    // ---- MLP1: relu(pool @ W1 + b1) ----
    {
        dim3 gA((KPM / 4 + 255) / 256, GG);
        k_splitA2<<<gA, 256>>>(p_pool, p_a2, GG, HF2, KPM);
        dim3 gB(KPM / 64, 512 / 32);
        k_splitBT2<<<gB, dim3(32, 8)>>>(W1, p_b2, HF2, 512, KPM);
        mma_gemm<<<2 * 4, 256, SMEM_MMA>>>(p_a2, p_b2, b1, p_m1,
                                           GG, 512, 512, KPM, 2, 4, 3);
    }

    // MLP tail (tiny)
    {
        dim3 grid(1, 2);
        sgemm<<<grid, 256>>>(p_m1, W2, b2, p_m2, GG, 128, 512, 1, 0);
    }
    {
        dim3 grid(1, 2);
        sgemm<<<grid, 256>>>(p_m2, W3, b3, out, GG, 64, 128, 1, 0);
    }
}

// round 5
// speedup vs baseline: 2.5385x; 1.0153x over previous
#include <cuda_runtime.h>
#include <cuda_bf16.h>
#include <cstdint>
#include <cstddef>

// ---------------- problem constants (fixed shapes) ----------------
#define NN    8000      // nodes
#define EE    32000     // raw edges
#define ETOT  40000     // edges + self loops
#define GG    256       // graphs
#define FF    680       // in-features per head
#define HH    10        // heads
#define HFD   6800      // H*F
#define HF2   13600     // 2*HF

// padded dims for tensor-core GEMMs
#define MP_G  8064      // 63*128  (rows of node matrices)
#define KP1   704       // GEMM1 K (680 padded to 64-mult)
#define KP2   6848      // GEMM2 K (6800 padded)
#define KPM   13632     // MLP1 K (13600 padded)
#define NPAD  6912      // 54*128  (N=6800 padded)

#define PCH   14        // ceil(KP2 / 512) float2 chunks per 256-thread block

// ---------------- scratch (static device allocations) ----------------
__device__ float g_xh [(size_t)NN * HFD];
__device__ float g_xw [(size_t)NN * HFD];
__device__ float g_h2 [(size_t)NN * HFD];
__device__ float g_als[NN * HH];
__device__ float g_ald[NN * HH];
__device__ float g_alpha[(size_t)ETOT * HH];
__device__ int   g_cnt[NN];
__device__ int   g_cur[NN];
__device__ int   g_start[NN + 1];
__device__ int   g_esrc[ETOT];
__device__ float g_dinv[NN];
__device__ int   g_pstart[GG];
__device__ int   g_pend[GG];
__device__ int   g_pcnt[GG];
__device__ float g_mlp1[GG * 512];
__device__ float g_mlp2[GG * 128];

// bf16 split panels: A=[hi|lo], Bt=[hi|lo] along K (each segment KP wide)
__device__ __nv_bfloat16 s_a2[(size_t)MP_G * (2 * KP2)];
__device__ __nv_bfloat16 s_b2[(size_t)NPAD * (2 * KP2)];

// ---------------- PTX helpers ----------------
__device__ __forceinline__ uint32_t smem_u32(const void* p) {
    uint32_t a;
    asm("{ .reg .u64 t; cvta.to.shared.u64 t, %1; cvt.u32.u64 %0, t; }" : "=r"(a) : "l"(p));
    return a;
}

__device__ __forceinline__ void cp16(uint32_t dst, const void* src) {
    asm volatile("cp.async.cg.shared.global [%0], [%1], 16;" :: "r"(dst), "l"(src));
}
#define CP_COMMIT() asm volatile("cp.async.commit_group;" ::: "memory")
__device__ __forceinline__ void cp_wait(int pend) {
    if (pend <= 0)      asm volatile("cp.async.wait_group 0;" ::: "memory");
    else if (pend == 1) asm volatile("cp.async.wait_group 1;" ::: "memory");
    else                asm volatile("cp.async.wait_group 2;" ::: "memory");
}

__device__ __forceinline__ void ldsm4(uint32_t* r, uint32_t addr) {
    asm volatile("ldmatrix.sync.aligned.m8n8.x4.shared.b16 {%0,%1,%2,%3}, [%4];"
                 : "=r"(r[0]), "=r"(r[1]), "=r"(r[2]), "=r"(r[3]) : "r"(addr));
}

__device__ __forceinline__ void mma16816(float* d, const uint32_t* a, uint32_t b0, uint32_t b1) {
    asm volatile("mma.sync.aligned.m16n8k16.row.col.f32.bf16.bf16.f32 "
                 "{%0,%1,%2,%3}, {%4,%5,%6,%7}, {%8,%9}, {%0,%1,%2,%3};"
                 : "+f"(d[0]), "+f"(d[1]), "+f"(d[2]), "+f"(d[3])
                 : "r"(a[0]), "r"(a[1]), "r"(a[2]), "r"(a[3]), "r"(b0), "r"(b1));
}

// smem tile addressing: 128 rows x 32 bf16 (64B/row), 16B chunks XOR-swizzled
__device__ __forceinline__ uint32_t sm_tile_off(int row, int chunk) {
    return (uint32_t)(row * 64 + ((chunk ^ ((row >> 1) & 3)) << 4));
}

// chunk c (0..3*CH0) -> source k-chunks in the [hi|lo] panels
__device__ __forceinline__ void chunk_map(int c, int CH0, int& kA, int& kB) {
    int seg = (c >= 2 * CH0) ? 2 : ((c >= CH0) ? 1 : 0);
    int r = c - seg * CH0;
    kA = r + ((seg == 1) ? CH0 : 0);   // seg1: A-lo
    kB = r + ((seg == 2) ? CH0 : 0);   // seg2: B-lo
}

// ---------------- mma.sync bf16 GEMM: C = A2[M,2KP] (x) B2t[N,2KP], 3 split terms ----------------
#define BM 128
#define BN 128
#define BK 32
#define STG 4
#define STAGE_BYTES 16384
#define SMEM_MMA (STG * STAGE_BYTES)

__global__ __launch_bounds__(256, 2) void mma_gemm(
    const __nv_bfloat16* __restrict__ A2, const __nv_bfloat16* __restrict__ B2,
    const float* __restrict__ bias, float* __restrict__ C,
    int M, int N, int ldc, int KP, int tiles_m, int tiles_n, int flags)
{
    extern __shared__ char smem[];
    uint32_t sb = smem_u32(smem);
    const int tid = threadIdx.x;
    const int wid = tid >> 5;
    const int lane = tid & 31;
    const int warp_m = wid & 3;
    const int warp_n = wid >> 2;

    int gm, gn;
    {
        const int GM = 8;
        int bid = blockIdx.x;
        int per = GM * tiles_n;
        int grp = bid / per;
        int fm  = grp * GM;
        int gsz = tiles_m - fm; if (gsz > GM) gsz = GM;
        int r = bid - grp * per;
        gm = fm + r % gsz;
        gn = r / gsz;
    }

    const int CH0 = KP / BK;
    const int CH = 3 * CH0;
    const int KA2 = 2 * KP;

    const int lrow = tid >> 1;
    const int lc0  = (tid & 1) * 2;
    const char* gA = (const char*)(A2 + (size_t)(gm * BM + lrow) * KA2);
    const char* gB = (const char*)(B2 + (size_t)(gn * BN + lrow) * KA2);
    uint32_t sAoff0 = sm_tile_off(lrow, lc0);
    uint32_t sAoff1 = sm_tile_off(lrow, lc0 + 1);

    uint32_t aoff[2][2], boff[4][2];
#pragma unroll
    for (int ks = 0; ks < 2; ks++) {
        int chunk = ks * 2 + (lane >> 4);
#pragma unroll
        for (int mi = 0; mi < 2; mi++)
            aoff[mi][ks] = sm_tile_off(warp_m * 32 + mi * 16 + (lane & 15), chunk);
#pragma unroll
        for (int g = 0; g < 4; g++)
            boff[g][ks] = 8192 + sm_tile_off(warp_n * 64 + g * 16 + (lane & 15), chunk);
    }

    float acc[2][8][4];
#pragma unroll
    for (int mi = 0; mi < 2; mi++)
#pragma unroll
        for (int ni = 0; ni < 8; ni++)
#pragma unroll
            for (int j = 0; j < 4; j++) acc[mi][ni][j] = 0.f;

    // prologue: preload 3 stages
#pragma unroll
    for (int c = 0; c < 3; c++) {
        int kA, kB; chunk_map(c, CH0, kA, kB);
        uint32_t stb = sb + c * STAGE_BYTES;
        long offA = (long)(kA * BK + lc0 * 8) * 2;
        long offB = (long)(kB * BK + lc0 * 8) * 2;
        cp16(stb + sAoff0, gA + offA);
        cp16(stb + sAoff1, gA + offA + 16);
        cp16(stb + 8192 + sAoff0, gB + offB);
        cp16(stb + 8192 + sAoff1, gB + offB + 16);
        CP_COMMIT();
    }

    for (int c = 0; c < CH; c++) {
        int pend = CH - 1 - c; if (pend > 2) pend = 2;
        cp_wait(pend);
        __syncthreads();

        uint32_t stb = sb + (c & (STG - 1)) * STAGE_BYTES;
#pragma unroll
        for (int ks = 0; ks < 2; ks++) {
            uint32_t a[2][4], b[4][4];
            ldsm4(a[0], stb + aoff[0][ks]);
            ldsm4(a[1], stb + aoff[1][ks]);
#pragma unroll
            for (int g = 0; g < 4; g++) ldsm4(b[g], stb + boff[g][ks]);
#pragma unroll
            for (int mi = 0; mi < 2; mi++)
#pragma unroll
                for (int ni = 0; ni < 8; ni++) {
                    int g = ni >> 1, h = ni & 1;
                    mma16816(acc[mi][ni], a[mi], b[g][h], b[g][h + 2]);
                }
        }

        if (c + 3 < CH) {
            int kA, kB; chunk_map(c + 3, CH0, kA, kB);
            uint32_t dtb = sb + ((c + 3) & (STG - 1)) * STAGE_BYTES;
            long offA = (long)(kA * BK + lc0 * 8) * 2;
            long offB = (long)(kB * BK + lc0 * 8) * 2;
            cp16(dtb + sAoff0, gA + offA);
            cp16(dtb + sAoff1, gA + offA + 16);
            cp16(dtb + 8192 + sAoff0, gB + offB);
            cp16(dtb + 8192 + sAoff1, gB + offB + 16);
            CP_COMMIT();
        }
    }

    // epilogue
    int row0 = gm * BM + warp_m * 32 + (lane >> 2);
    int col0 = gn * BN + warp_n * 64 + (lane & 3) * 2;
#pragma unroll
    for (int mi = 0; mi < 2; mi++) {
#pragma unroll
        for (int ni = 0; ni < 8; ni++) {
            int r = row0 + mi * 16;
            int cc = col0 + ni * 8;
#pragma unroll
            for (int half = 0; half < 2; half++) {
                int rr = r + half * 8;
                if (rr < M) {
                    float v0 = acc[mi][ni][half * 2 + 0];
                    float v1 = acc[mi][ni][half * 2 + 1];
                    if (cc < N) {
                        float v = v0;
                        if (flags & 1) v += bias[cc];
                        if (flags & 2) v = fmaxf(v, 0.f);
                        C[(size_t)rr * ldc + cc] = v;
                    }
                    if (cc + 1 < N) {
                        float v = v1;
                        if (flags & 1) v += bias[cc + 1];
                        if (flags & 2) v = fmaxf(v, 0.f);
                        C[(size_t)rr * ldc + cc + 1] = v;
                    }
                }
            }
        }
    }
}

// ---------------- conversion kernels ----------------
// A[M,K] fp32 -> dst[Mp, 2KP] bf16: [hi | lo]; pads -> 0.  1 thread = 4 elems.
__global__ void k_splitA2(const float* __restrict__ src, __nv_bfloat16* __restrict__ dst,
                          int M, int K, int KP)
{
    int k = (blockIdx.x * 256 + threadIdx.x) * 4;
    int m = blockIdx.y;
    if (k >= KP) return;
    float4 v = make_float4(0.f, 0.f, 0.f, 0.f);
    if (m < M && k < K) v = *reinterpret_cast<const float4*>(&src[(size_t)m * K + k]);
    __nv_bfloat16 h0 = __float2bfloat16(v.x), h1 = __float2bfloat16(v.y);
    __nv_bfloat16 h2 = __float2bfloat16(v.z), h3 = __float2bfloat16(v.w);
    __nv_bfloat16 l0 = __float2bfloat16(v.x - __bfloat162float(h0));
    __nv_bfloat16 l1 = __float2bfloat16(v.y - __bfloat162float(h1));
    __nv_bfloat16 l2 = __float2bfloat16(v.z - __bfloat162float(h2));
    __nv_bfloat16 l3 = __float2bfloat16(v.w - __bfloat162float(h3));
    uint2 hp, lp;
    hp.x = ((uint32_t)__bfloat16_as_ushort(h1) << 16) | __bfloat16_as_ushort(h0);
    hp.y = ((uint32_t)__bfloat16_as_ushort(h3) << 16) | __bfloat16_as_ushort(h2);
    lp.x = ((uint32_t)__bfloat16_as_ushort(l1) << 16) | __bfloat16_as_ushort(l0);
    lp.y = ((uint32_t)__bfloat16_as_ushort(l3) << 16) | __bfloat16_as_ushort(l2);
    size_t base = (size_t)m * (2 * KP);
    *reinterpret_cast<uint2*>(&dst[base + k]) = hp;
    *reinterpret_cast<uint2*>(&dst[base + KP + k]) = lp;
}

// B[K,N] fp32 -> transposed dst[Np, 2KP] bf16: [hi | lo]; pads -> 0.
__global__ void k_splitBT2(const float* __restrict__ src, __nv_bfloat16* __restrict__ dst,
                           int K, int N, int KP)
{
    __shared__ float t[64][33];
    int k0 = blockIdx.x * 64, n0 = blockIdx.y * 32;
    int tx = threadIdx.x, ty = threadIdx.y;   // 32 x 8
#pragma unroll
    for (int it = 0; it < 8; it++) {
        int k = k0 + ty + it * 8;
        int n = n0 + tx;
        t[ty + it * 8][tx] = (k < K && n < N) ? src[(size_t)k * N + n] : 0.f;
    }
    __syncthreads();
    int uid = ty * 32 + tx;
    int nl = uid >> 3;            // 0..31
    int kg = (uid & 7) * 8;       // 0,8,...,56
    size_t base = (size_t)(n0 + nl) * (2 * KP) + k0;
#pragma unroll
    for (int q = 0; q < 4; q++) {
        int kk = kg + q * 2;
        float v0 = t[kk][nl], v1 = t[kk + 1][nl];
        __nv_bfloat16 h0 = __float2bfloat16(v0), h1 = __float2bfloat16(v1);
        __nv_bfloat16 l0 = __float2bfloat16(v0 - __bfloat162float(h0));
        __nv_bfloat16 l1 = __float2bfloat16(v1 - __bfloat162float(h1));
        uint32_t hp = ((uint32_t)__bfloat16_as_ushort(h1) << 16) | __bfloat16_as_ushort(h0);
        uint32_t lp = ((uint32_t)__bfloat16_as_ushort(l1) << 16) | __bfloat16_as_ushort(l0);
        *reinterpret_cast<uint32_t*>(&dst[base + kk]) = hp;
        *reinterpret_cast<uint32_t*>(&dst[base + KP + kk]) = lp;
    }
}

// ---------------- scalar SGEMM (tiny MLP tail layers) ----------------
__global__ __launch_bounds__(256) void sgemm(const float* __restrict__ A,
                                             const float* __restrict__ B,
                                             const float* __restrict__ bias,
                                             float* __restrict__ C,
                                             int M, int N, int K,
                                             int hasBias, int doRelu) {
    __shared__ float As[8][128];
    __shared__ float Bs[8][128];
    const int tid   = threadIdx.x;
    const int tileM = blockIdx.y * 128;
    const int tileN = blockIdx.x * 128;

    const int aRow = tid >> 1;
    const int aK4  = (tid & 1) * 4;
    const int bRow = tid >> 5;
    const int bCol = (tid & 31) * 4;
    const int ty   = tid >> 4;
    const int tx   = tid & 15;

    float acc[8][8];
#pragma unroll
    for (int i = 0; i < 8; i++)
#pragma unroll
        for (int j = 0; j < 8; j++) acc[i][j] = 0.f;

    for (int k0 = 0; k0 < K; k0 += 8) {
        float4 av = make_float4(0.f, 0.f, 0.f, 0.f);
        int gr = tileM + aRow;
        if (gr < M) av = *reinterpret_cast<const float4*>(&A[(size_t)gr * K + k0 + aK4]);
        As[aK4 + 0][aRow] = av.x;
        As[aK4 + 1][aRow] = av.y;
        As[aK4 + 2][aRow] = av.z;
        As[aK4 + 3][aRow] = av.w;

        float4 bv = make_float4(0.f, 0.f, 0.f, 0.f);
        int gc = tileN + bCol;
        const float* bp = &B[(size_t)(k0 + bRow) * N + gc];
        if (gc + 3 < N) {
            bv = *reinterpret_cast<const float4*>(bp);
        } else {
            if (gc + 0 < N) bv.x = bp[0];
            if (gc + 1 < N) bv.y = bp[1];
            if (gc + 2 < N) bv.z = bp[2];
            if (gc + 3 < N) bv.w = bp[3];
        }
        *reinterpret_cast<float4*>(&Bs[bRow][bCol]) = bv;

        __syncthreads();
#pragma unroll
        for (int kk = 0; kk < 8; kk++) {
            float a[8], b[8];
            *reinterpret_cast<float4*>(&a[0]) = *reinterpret_cast<float4*>(&As[kk][ty * 8]);
            *reinterpret_cast<float4*>(&a[4]) = *reinterpret_cast<float4*>(&As[kk][ty * 8 + 4]);
            *reinterpret_cast<float4*>(&b[0]) = *reinterpret_cast<float4*>(&Bs[kk][tx * 8]);
            *reinterpret_cast<float4*>(&b[4]) = *reinterpret_cast<float4*>(&Bs[kk][tx * 8 + 4]);
#pragma unroll
            for (int i = 0; i < 8; i++)
#pragma unroll
                for (int j = 0; j < 8; j++) acc[i][j] = fmaf(a[i], b[j], acc[i][j]);
        }
        __syncthreads();
    }

#pragma unroll
    for (int i = 0; i < 8; i++) {
        int row = tileM + ty * 8 + i;
        if (row >= M) continue;
#pragma unroll
        for (int j = 0; j < 8; j++) {
            int col = tileN + tx * 8 + j;
            if (col < N) {
                float v = acc[i][j];
                if (hasBias) v += bias[col];
                if (doRelu) v = fmaxf(v, 0.f);
                C[(size_t)row * N + col] = v;
            }
        }
    }
}

// ---------------- CSR build ----------------
__global__ void k_init() {
    int i = blockIdx.x * blockDim.x + threadIdx.x;
    if (i < NN) { g_cnt[i] = 0; g_cur[i] = 0; }
    if (i < GG) { g_pstart[i] = 0x7fffffff; g_pend[i] = -1; g_pcnt[i] = 0; }
}

__global__ void k_count(const int* __restrict__ ei) {
    int k = blockIdx.x * blockDim.x + threadIdx.x;
    if (k >= ETOT) return;
    int dst = (k < EE) ? ei[EE + k] : (k - EE);
    atomicAdd(&g_cnt[dst], 1);
}

__global__ __launch_bounds__(1024) void k_scan() {
    __shared__ int sd[1024];
    __shared__ int scarry;
    int tid = threadIdx.x;
    if (tid == 0) { scarry = 0; g_start[0] = 0; }
    __syncthreads();
    for (int base = 0; base < NN; base += 1024) {
        int v = (base + tid < NN) ? g_cnt[base + tid] : 0;
        sd[tid] = v;
        __syncthreads();
        for (int o = 1; o < 1024; o <<= 1) {
            int t = (tid >= o) ? sd[tid - o] : 0;
            __syncthreads();
            sd[tid] += t;
            __syncthreads();
        }
        int run = scarry;
        if (base + tid < NN) g_start[base + tid + 1] = run + sd[tid];
        __syncthreads();
        if (tid == 1023) scarry = run + sd[1023];
        __syncthreads();
    }
}

__global__ void k_scatter(const int* __restrict__ ei) {
    int k = blockIdx.x * blockDim.x + threadIdx.x;
    if (k >= ETOT) return;
    int src = (k < EE) ? ei[k]      : (k - EE);
    int dst = (k < EE) ? ei[EE + k] : (k - EE);
    int pos = g_start[dst] + atomicAdd(&g_cur[dst], 1);
    g_esrc[pos] = src;
}

__global__ void k_dinv() {
    int i = blockIdx.x * blockDim.x + threadIdx.x;
    if (i < NN) g_dinv[i] = rsqrtf((float)g_cnt[i]);
}

// ---------------- attention ----------------
__global__ void k_attn(const float* __restrict__ xh, const float* __restrict__ a_s,
                       const float* __restrict__ a_d) {
    int n = blockIdx.x;
    int w = threadIdx.x >> 5;
    int lane = threadIdx.x & 31;
    if (w >= HH) return;
    const float* row = xh + (size_t)n * HFD + w * FF;
    const float* as  = a_s + w * FF;
    const float* ad  = a_d + w * FF;
    float s1 = 0.f, s2 = 0.f;
    for (int f = lane; f < FF; f += 32) {
        float v = row[f];
        s1 = fmaf(v, as[f], s1);
        s2 = fmaf(v, ad[f], s2);
    }
#pragma unroll
    for (int o = 16; o; o >>= 1) {
        s1 += __shfl_down_sync(0xffffffffu, s1, o);
        s2 += __shfl_down_sync(0xffffffffu, s2, o);
    }
    if (lane == 0) { g_als[n * HH + w] = s1; g_ald[n * HH + w] = s2; }
}

// per-node segment softmax over CSR edges; warp per node, lane = head
__global__ void k_softmax() {
    int node = blockIdx.x * blockDim.y + threadIdx.y;
    if (node >= NN) return;
    int lane = threadIdx.x;
    bool act = lane < HH;
    int s = g_start[node], e = g_start[node + 1];
    float ald_v = act ? g_ald[node * HH + lane] : 0.f;
    float mx = -3.0e38f;
    for (int p = s; p < e; p++) {
        int src = g_esrc[p];
        if (act) {
            float v = g_als[src * HH + lane] + ald_v;
            v = fmaxf(v, 0.2f * v);
            mx = fmaxf(mx, v);
        }
    }
    float z = 0.f;
    for (int p = s; p < e; p++) {
        int src = g_esrc[p];
        if (act) {
            float v = g_als[src * HH + lane] + ald_v;
            v = fmaxf(v, 0.2f * v);
            float ex = expf(v - mx);
            g_alpha[(size_t)p * HH + lane] = ex;
            z += ex;
        }
    }
    float inv = 1.f / (z + 1e-16f);
    for (int p = s; p < e; p++)
        if (act) g_alpha[(size_t)p * HH + lane] *= inv;
}

// ---------------- GAT aggregation fused with A-panel split (grid = MP_G) ----------------
__global__ __launch_bounds__(256) void k_gat_agg_split(const float* __restrict__ bias) {
    int n = blockIdx.x, tid = threadIdx.x;
    __nv_bfloat16* arow = s_a2 + (size_t)n * (2 * KP2);
    if (n >= NN) {
        for (int k = tid; k < 2 * KP2 / 2; k += 256)
            reinterpret_cast<uint32_t*>(arow)[k] = 0;
        return;
    }
    int s = g_start[n], e = g_start[n + 1];
    float2 acc[PCH];
    int hidx[PCH];
#pragma unroll
    for (int i = 0; i < PCH; i++) {
        int f = 2 * tid + 512 * i;
        hidx[i] = (f < HFD) ? (f / FF) : 0;
        acc[i].x = (f < HFD) ? bias[f] : 0.f;
        acc[i].y = (f + 1 < HFD) ? bias[f + 1] : 0.f;
    }
    for (int p = s; p < e; p++) {
        int src = g_esrc[p];
        const float2* xr = reinterpret_cast<const float2*>(g_xh + (size_t)src * HFD);
        const float* al = g_alpha + (size_t)p * HH;
#pragma unroll
        for (int i = 0; i < PCH; i++) {
            int f = 2 * tid + 512 * i;
            if (f < HFD) {
                float2 v = xr[f >> 1];
                float a = al[hidx[i]];
                acc[i].x = fmaf(a, v.x, acc[i].x);
                acc[i].y = fmaf(a, v.y, acc[i].y);
            }
        }
    }
#pragma unroll
    for (int i = 0; i < PCH; i++) {
        int f = 2 * tid + 512 * i;
        if (f < KP2) {
            float vx = (f < HFD) ? fmaxf(acc[i].x, 0.f) : 0.f;
            float vy = (f + 1 < HFD) ? fmaxf(acc[i].y, 0.f) : 0.f;
            __nv_bfloat16 hx = __float2bfloat16(vx), hy = __float2bfloat16(vy);
            __nv_bfloat16 lx = __float2bfloat16(vx - __bfloat162float(hx));
            __nv_bfloat16 ly = __float2bfloat16(vy - __bfloat162float(hy));
            uint32_t hp = ((uint32_t)__bfloat16_as_ushort(hy) << 16) | __bfloat16_as_ushort(hx);
            uint32_t lp = ((uint32_t)__bfloat16_as_ushort(ly) << 16) | __bfloat16_as_ushort(lx);
            *reinterpret_cast<uint32_t*>(&arow[f]) = hp;
            *reinterpret_cast<uint32_t*>(&arow[KP2 + f]) = lp;
        }
    }
}

// ---------------- GCN aggregation (fp32 out, bias+relu fused) ----------------
#define FCH 27
__global__ __launch_bounds__(256) void k_gcn_agg(const float* __restrict__ bias) {
    int n = blockIdx.x, tid = threadIdx.x;
    int s = g_start[n], e = g_start[n + 1];
    float dv = g_dinv[n];
    float acc[FCH];
#pragma unroll
    for (int i = 0; i < FCH; i++) {
        int f = tid + i * 256;
        acc[i] = (f < HFD) ? bias[f] : 0.f;
    }
    for (int p = s; p < e; p++) {
        int src = g_esrc[p];
        float coef = g_dinv[src] * dv;
        const float* xr = g_xw + (size_t)src * HFD;
#pragma unroll
        for (int i = 0; i < FCH; i++) {
            int f = tid + i * 256;
            if (f < HFD) acc[i] = fmaf(coef, xr[f], acc[i]);
        }
    }
    float* o = g_h2 + (size_t)n * HFD;
#pragma unroll
    for (int i = 0; i < FCH; i++) {
        int f = tid + i * 256;
        if (f < HFD) o[f] = fmaxf(acc[i], 0.f);
    }
}

// ---------------- pooling fused with MLP1 A-panel split ----------------
__global__ void k_ranges(const int* __restrict__ batch) {
    int i = blockIdx.x * blockDim.x + threadIdx.x;
    if (i >= NN) return;
    int b = batch[i];
    if (b >= 0 && b < GG) {
        atomicMin(&g_pstart[b], i);
        atomicMax(&g_pend[b], i);
        atomicAdd(&g_pcnt[b], 1);
    }
}

__device__ __forceinline__ void bf_split_store(__nv_bfloat16* hi, __nv_bfloat16* lo, float v) {
    __nv_bfloat16 h = __float2bfloat16(v);
    *hi = h;
    *lo = __float2bfloat16(v - __bfloat162float(h));
}

__global__ __launch_bounds__(256) void k_pool_split() {
    int g = blockIdx.y;
    int f = blockIdx.x * blockDim.x + threadIdx.x;
    if (f >= HFD) return;
    int s = g_pstart[g], e = g_pend[g];
    float mx = -3.0e38f, sm = 0.f;
    for (int n = s; n <= e; n++) {
        float v = g_h2[(size_t)n * HFD + f];
        mx = fmaxf(mx, v);
        sm += v;
    }
    float gap = sm / (float)g_pcnt[g];
    __nv_bfloat16* row = s_a2 + (size_t)g * (2 * KPM);
    bf_split_store(&row[f],             &row[KPM + f],             mx);
    bf_split_store(&row[HFD + f],       &row[KPM + HFD + f],       gap);
}

// zero pad cols [HF2, KPM) of both segments of the MLP1 A panel
__global__ void k_pool_pad() {
    int g = blockIdx.x;
    int t = threadIdx.x;            // 32 threads
    __nv_bfloat16* row = s_a2 + (size_t)g * (2 * KPM);
    row[HF2 + t] = __float2bfloat16(0.f);
    row[KPM + HF2 + t] = __float2bfloat16(0.f);
}

// ---------------- launch ----------------
extern "C" void kernel_launch(void* const* d_in, const int* in_sizes, int n_in,
                              void* d_out, int out_size) {
    const float* x     = (const float*)d_in[0];
    const int*   ei    = (const int*)  d_in[1];
    const int*   batch = (const int*)  d_in[2];
    const float* W_gat = (const float*)d_in[3];
    const float* a_src = (const float*)d_in[4];
    const float* a_dst = (const float*)d_in[5];
    const float* b_gat = (const float*)d_in[6];
    const float* W_gcn = (const float*)d_in[7];
    const float* b_gcn = (const float*)d_in[8];
    const float* W1    = (const float*)d_in[9];
    const float* b1    = (const float*)d_in[10];
    const float* W2    = (const float*)d_in[11];
    const float* b2    = (const float*)d_in[12];
    const float* W3    = (const float*)d_in[13];
    const float* b3    = (const float*)d_in[14];
    float* out = (float*)d_out;

    float *p_xh, *p_xw, *p_m1, *p_m2;
    __nv_bfloat16 *p_a2, *p_b2;
    cudaGetSymbolAddress((void**)&p_xh,   g_xh);
    cudaGetSymbolAddress((void**)&p_xw,   g_xw);
    cudaGetSymbolAddress((void**)&p_m1,   g_mlp1);
    cudaGetSymbolAddress((void**)&p_m2,   g_mlp2);
    cudaGetSymbolAddress((void**)&p_a2,   s_a2);
    cudaGetSymbolAddress((void**)&p_b2,   s_b2);

    cudaFuncSetAttribute(mma_gemm, cudaFuncAttributeMaxDynamicSharedMemorySize, SMEM_MMA);

    const int TM = MP_G / 128;   // 63
    const int TN = NPAD / 128;   // 54

    // CSR build + degrees
    k_init<<<(NN + 255) / 256, 256>>>();
    k_count<<<(ETOT + 255) / 256, 256>>>(ei);
    k_scan<<<1, 1024>>>();
    k_scatter<<<(ETOT + 255) / 256, 256>>>(ei);
    k_dinv<<<(NN + 255) / 256, 256>>>();

    // ---- GEMM1: xh = x @ W_gat ----
    {
        dim3 gA((KP1 / 4 + 255) / 256, MP_G);
        k_splitA2<<<gA, 256>>>(x, p_a2, NN, FF, KP1);
        dim3 gB(KP1 / 64, NPAD / 32);
        k_splitBT2<<<gB, dim3(32, 8)>>>(W_gat, p_b2, FF, HFD, KP1);
        mma_gemm<<<TM * TN, 256, SMEM_MMA>>>(p_a2, p_b2, nullptr, p_xh,
                                             NN, HFD, HFD, KP1, TM, TN, 0);
    }

    k_attn<<<NN, 320>>>(p_xh, a_src, a_dst);
    k_softmax<<<(NN + 7) / 8, dim3(32, 8)>>>();
    // GAT aggregation writes the GEMM2 A-panel (bf16 hi/lo) directly
    k_gat_agg_split<<<MP_G, 256>>>(b_gat);

    // ---- GEMM2: xw = h @ W_gcn ----
    {
        dim3 gB(KP2 / 64, NPAD / 32);
        k_splitBT2<<<gB, dim3(32, 8)>>>(W_gcn, p_b2, HFD, HFD, KP2);
        mma_gemm<<<TM * TN, 256, SMEM_MMA>>>(p_a2, p_b2, nullptr, p_xw,
                                             NN, HFD, HFD, KP2, TM, TN, 0);
    }

    k_gcn_agg<<<NN, 256>>>(b_gcn);

    // pooling (writes MLP1 A-panel directly)
    k_ranges<<<(NN + 255) / 256, 256>>>(batch);
    {
        dim3 grid((HFD + 255) / 256, GG);
        k_pool_split<<<grid, 256>>>();
        k_pool_pad<<<GG, 32>>>();
    }

    // ---- MLP1: relu(pool @ W1 + b1) ----
    {
        dim3 gB(KPM / 64, 512 / 32);
        k_splitBT2<<<gB, dim3(32, 8)>>>(W1, p_b2, HF2, 512, KPM);
        mma_gemm<<<2 * 4, 256, SMEM_MMA>>>(p_a2, p_b2, b1, p_m1,
                                           GG, 512, 512, KPM, 2, 4, 3);
    }

    // MLP tail (tiny)
    {
        dim3 grid(1, 2);
        sgemm<<<grid, 256>>>(p_m1, W2, b2, p_m2, GG, 128, 512, 1, 0);
    }
    {
        dim3 grid(1, 2);
        sgemm<<<grid, 256>>>(p_m2, W3, b3, out, GG, 64, 128, 1, 0);
    }
}

// round 6
// speedup vs baseline: 2.8681x; 1.1298x over previous
#include <cuda_runtime.h>
#include <cuda_bf16.h>
#include <cstdint>
#include <cstddef>

// ---------------- problem constants (fixed shapes) ----------------
#define NN    8000      // nodes
#define EE    32000     // raw edges
#define ETOT  40000     // edges + self loops
#define GG    256       // graphs
#define FF    680       // in-features per head
#define HH    10        // heads
#define HFD   6800      // H*F
#define HF2   13600     // 2*HF

// padded dims for tensor-core GEMMs
#define MP_G  8064      // 63*128  (rows of node matrices)
#define KP1   704       // GEMM1 K (680 padded to 64-mult)
#define KP2   6848      // GEMM2 K (6800 padded)
#define KPM   13632     // MLP1 K (13600 padded)
#define NPAD  6912      // 54*128  (N=6800 padded)

#define PCH   14        // ceil(KP2 / 512) float2 chunks per 256-thread block

// ---------------- scratch (static device allocations) ----------------
__device__ float g_xh [(size_t)NN * HFD];
__device__ float g_xw [(size_t)NN * HFD];
__device__ float g_h2 [(size_t)NN * HFD];
__device__ float g_als[NN * HH];
__device__ float g_ald[NN * HH];
__device__ float g_alpha[(size_t)ETOT * HH];
__device__ int   g_cnt[NN];
__device__ int   g_cur[NN];
__device__ int   g_start[NN + 1];
__device__ int   g_esrc[ETOT];
__device__ float g_dinv[NN];
__device__ int   g_pstart[GG];
__device__ int   g_pend[GG];
__device__ int   g_pcnt[GG];
__device__ float g_mlp1[GG * 512];
__device__ float g_mlp2[GG * 128];

// bf16 split panels: A=[hi|lo], Bt=[hi|lo] along K (each segment KP wide)
__device__ __nv_bfloat16 s_a2[(size_t)MP_G * (2 * KP2)];
__device__ __nv_bfloat16 s_b2[(size_t)NPAD * (2 * KP2)];

// ---------------- PTX helpers ----------------
__device__ __forceinline__ uint32_t smem_u32(const void* p) {
    uint32_t a;
    asm("{ .reg .u64 t; cvta.to.shared.u64 t, %1; cvt.u32.u64 %0, t; }" : "=r"(a) : "l"(p));
    return a;
}

__device__ __forceinline__ void cp16(uint32_t dst, const void* src) {
    asm volatile("cp.async.cg.shared.global [%0], [%1], 16;" :: "r"(dst), "l"(src));
}
#define CP_COMMIT() asm volatile("cp.async.commit_group;" ::: "memory")
__device__ __forceinline__ void cp_wait(int pend) {
    if (pend <= 0)      asm volatile("cp.async.wait_group 0;" ::: "memory");
    else                asm volatile("cp.async.wait_group 1;" ::: "memory");
}

__device__ __forceinline__ void ldsm4(uint32_t* r, uint32_t addr) {
    asm volatile("ldmatrix.sync.aligned.m8n8.x4.shared.b16 {%0,%1,%2,%3}, [%4];"
                 : "=r"(r[0]), "=r"(r[1]), "=r"(r[2]), "=r"(r[3]) : "r"(addr));
}

__device__ __forceinline__ void mma16816(float* d, const uint32_t* a, uint32_t b0, uint32_t b1) {
    asm volatile("mma.sync.aligned.m16n8k16.row.col.f32.bf16.bf16.f32 "
                 "{%0,%1,%2,%3}, {%4,%5,%6,%7}, {%8,%9}, {%0,%1,%2,%3};"
                 : "+f"(d[0]), "+f"(d[1]), "+f"(d[2]), "+f"(d[3])
                 : "r"(a[0]), "r"(a[1]), "r"(a[2]), "r"(a[3]), "r"(b0), "r"(b1));
}

// smem sub-tile addressing: 128 rows x 32 bf16 (64B/row), 16B chunks XOR-swizzled
__device__ __forceinline__ uint32_t sm_tile_off(int row, int chunk) {
    return (uint32_t)(row * 64 + ((chunk ^ ((row >> 1) & 3)) << 4));
}

// ---------------- mma.sync bf16 GEMM, shared-load 3-term split ----------------
// Per k-chunk loads Ahi/Alo/Bhi/Blo sub-tiles (8KB each) and computes
// AhiBhi + AloBhi + AhiBlo into fp32 accumulators.
#define BM 128
#define BN 128
#define BK 32
#define STG 3
#define SUB_BYTES   8192
#define STAGE_BYTES 32768
#define SMEM_MMA (STG * STAGE_BYTES)

__global__ __launch_bounds__(256, 2) void mma_gemm(
    const __nv_bfloat16* __restrict__ A2, const __nv_bfloat16* __restrict__ B2,
    const float* __restrict__ bias, float* __restrict__ C,
    int M, int N, int ldc, int KP, int tiles_m, int tiles_n, int flags)
{
    extern __shared__ char smem[];
    uint32_t sb = smem_u32(smem);
    const int tid = threadIdx.x;
    const int wid = tid >> 5;
    const int lane = tid & 31;
    const int warp_m = wid & 3;
    const int warp_n = wid >> 2;

    int gm, gn;
    {
        const int GM = 8;
        int bid = blockIdx.x;
        int per = GM * tiles_n;
        int grp = bid / per;
        int fm  = grp * GM;
        int gsz = tiles_m - fm; if (gsz > GM) gsz = GM;
        int r = bid - grp * per;
        gm = fm + r % gsz;
        gn = r / gsz;
    }

    const int CH = KP / BK;
    const int KA2 = 2 * KP;

    // per-thread cp.async coords: 2 (row,chunk) pairs per sub-tile
    int row0 = (tid * 2) >> 2,     ch0 = (tid * 2) & 3;
    int row1 = (tid * 2 + 1) >> 2, ch1 = (tid * 2 + 1) & 3;
    const __nv_bfloat16* pA0 = A2 + (size_t)(gm * BM + row0) * KA2 + ch0 * 8;
    const __nv_bfloat16* pA1 = A2 + (size_t)(gm * BM + row1) * KA2 + ch1 * 8;
    const __nv_bfloat16* pB0 = B2 + (size_t)(gn * BN + row0) * KA2 + ch0 * 8;
    const __nv_bfloat16* pB1 = B2 + (size_t)(gn * BN + row1) * KA2 + ch1 * 8;
    uint32_t so0 = sm_tile_off(row0, ch0);
    uint32_t so1 = sm_tile_off(row1, ch1);

    // ldmatrix offsets within a stage
    uint32_t aoff[2][2], boff[4][2];
#pragma unroll
    for (int ks = 0; ks < 2; ks++) {
        int chunk = ks * 2 + (lane >> 4);
#pragma unroll
        for (int mi = 0; mi < 2; mi++)
            aoff[mi][ks] = sm_tile_off(warp_m * 32 + mi * 16 + (lane & 15), chunk);
#pragma unroll
        for (int g = 0; g < 4; g++)
            boff[g][ks] = 2 * SUB_BYTES + sm_tile_off(warp_n * 64 + g * 16 + (lane & 15), chunk);
    }

    float acc[2][8][4];
#pragma unroll
    for (int mi = 0; mi < 2; mi++)
#pragma unroll
        for (int ni = 0; ni < 8; ni++)
#pragma unroll
            for (int j = 0; j < 4; j++) acc[mi][ni][j] = 0.f;

    // preload chunks 0,1
#pragma unroll
    for (int c = 0; c < 2 && c < CH; c++) {
        uint32_t stb = sb + c * STAGE_BYTES;
        int ko = c * BK;
        cp16(stb + so0,                 pA0 + ko);
        cp16(stb + so1,                 pA1 + ko);
        cp16(stb + SUB_BYTES + so0,     pA0 + KP + ko);
        cp16(stb + SUB_BYTES + so1,     pA1 + KP + ko);
        cp16(stb + 2 * SUB_BYTES + so0, pB0 + ko);
        cp16(stb + 2 * SUB_BYTES + so1, pB1 + ko);
        cp16(stb + 3 * SUB_BYTES + so0, pB0 + KP + ko);
        cp16(stb + 3 * SUB_BYTES + so1, pB1 + KP + ko);
        CP_COMMIT();
    }

    int s = 0;        // buffer of chunk c
    int sload = 2;    // buffer of chunk c+2
    for (int c = 0; c < CH; c++) {
        cp_wait((CH - 1 - c) >= 1 ? 1 : 0);
        __syncthreads();

        if (c + 2 < CH) {
            uint32_t dtb = sb + sload * STAGE_BYTES;
            int ko = (c + 2) * BK;
            cp16(dtb + so0,                 pA0 + ko);
            cp16(dtb + so1,                 pA1 + ko);
            cp16(dtb + SUB_BYTES + so0,     pA0 + KP + ko);
            cp16(dtb + SUB_BYTES + so1,     pA1 + KP + ko);
            cp16(dtb + 2 * SUB_BYTES + so0, pB0 + ko);
            cp16(dtb + 2 * SUB_BYTES + so1, pB1 + ko);
            cp16(dtb + 3 * SUB_BYTES + so0, pB0 + KP + ko);
            cp16(dtb + 3 * SUB_BYTES + so1, pB1 + KP + ko);
            CP_COMMIT();
        }

        uint32_t stb = sb + s * STAGE_BYTES;
#pragma unroll
        for (int ks = 0; ks < 2; ks++) {
            uint32_t ahi[2][4], alo[2][4];
            ldsm4(ahi[0], stb + aoff[0][ks]);
            ldsm4(ahi[1], stb + aoff[1][ks]);
            ldsm4(alo[0], stb + SUB_BYTES + aoff[0][ks]);
            ldsm4(alo[1], stb + SUB_BYTES + aoff[1][ks]);
#pragma unroll
            for (int g = 0; g < 4; g++) {
                uint32_t bh[4], bl[4];
                ldsm4(bh, stb + boff[g][ks]);
                ldsm4(bl, stb + SUB_BYTES + boff[g][ks]);
#pragma unroll
                for (int mi = 0; mi < 2; mi++) {
#pragma unroll
                    for (int h = 0; h < 2; h++) {
                        mma16816(acc[mi][g * 2 + h], ahi[mi], bh[h], bh[h + 2]);
                        mma16816(acc[mi][g * 2 + h], alo[mi], bh[h], bh[h + 2]);
                        mma16816(acc[mi][g * 2 + h], ahi[mi], bl[h], bl[h + 2]);
                    }
                }
            }
        }
        s++; if (s == STG) s = 0;
        sload++; if (sload == STG) sload = 0;
    }

    // epilogue
    int erow0 = gm * BM + warp_m * 32 + (lane >> 2);
    int ecol0 = gn * BN + warp_n * 64 + (lane & 3) * 2;
#pragma unroll
    for (int mi = 0; mi < 2; mi++) {
#pragma unroll
        for (int ni = 0; ni < 8; ni++) {
            int r = erow0 + mi * 16;
            int cc = ecol0 + ni * 8;
#pragma unroll
            for (int half = 0; half < 2; half++) {
                int rr = r + half * 8;
                if (rr < M) {
                    float v0 = acc[mi][ni][half * 2 + 0];
                    float v1 = acc[mi][ni][half * 2 + 1];
                    if (cc < N) {
                        float v = v0;
                        if (flags & 1) v += bias[cc];
                        if (flags & 2) v = fmaxf(v, 0.f);
                        C[(size_t)rr * ldc + cc] = v;
                    }
                    if (cc + 1 < N) {
                        float v = v1;
                        if (flags & 1) v += bias[cc + 1];
                        if (flags & 2) v = fmaxf(v, 0.f);
                        C[(size_t)rr * ldc + cc + 1] = v;
                    }
                }
            }
        }
    }
}

// ---------------- conversion kernels ----------------
__global__ void k_splitA2(const float* __restrict__ src, __nv_bfloat16* __restrict__ dst,
                          int M, int K, int KP)
{
    int k = (blockIdx.x * 256 + threadIdx.x) * 4;
    int m = blockIdx.y;
    if (k >= KP) return;
    float4 v = make_float4(0.f, 0.f, 0.f, 0.f);
    if (m < M && k < K) v = *reinterpret_cast<const float4*>(&src[(size_t)m * K + k]);
    __nv_bfloat16 h0 = __float2bfloat16(v.x), h1 = __float2bfloat16(v.y);
    __nv_bfloat16 h2 = __float2bfloat16(v.z), h3 = __float2bfloat16(v.w);
    __nv_bfloat16 l0 = __float2bfloat16(v.x - __bfloat162float(h0));
    __nv_bfloat16 l1 = __float2bfloat16(v.y - __bfloat162float(h1));
    __nv_bfloat16 l2 = __float2bfloat16(v.z - __bfloat162float(h2));
    __nv_bfloat16 l3 = __float2bfloat16(v.w - __bfloat162float(h3));
    uint2 hp, lp;
    hp.x = ((uint32_t)__bfloat16_as_ushort(h1) << 16) | __bfloat16_as_ushort(h0);
    hp.y = ((uint32_t)__bfloat16_as_ushort(h3) << 16) | __bfloat16_as_ushort(h2);
    lp.x = ((uint32_t)__bfloat16_as_ushort(l1) << 16) | __bfloat16_as_ushort(l0);
    lp.y = ((uint32_t)__bfloat16_as_ushort(l3) << 16) | __bfloat16_as_ushort(l2);
    size_t base = (size_t)m * (2 * KP);
    *reinterpret_cast<uint2*>(&dst[base + k]) = hp;
    *reinterpret_cast<uint2*>(&dst[base + KP + k]) = lp;
}

__global__ void k_splitBT2(const float* __restrict__ src, __nv_bfloat16* __restrict__ dst,
                           int K, int N, int KP)
{
    __shared__ float t[64][33];
    int k0 = blockIdx.x * 64, n0 = blockIdx.y * 32;
    int tx = threadIdx.x, ty = threadIdx.y;   // 32 x 8
#pragma unroll
    for (int it = 0; it < 8; it++) {
        int k = k0 + ty + it * 8;
        int n = n0 + tx;
        t[ty + it * 8][tx] = (k < K && n < N) ? src[(size_t)k * N + n] : 0.f;
    }
    __syncthreads();
    int uid = ty * 32 + tx;
    int nl = uid >> 3;
    int kg = (uid & 7) * 8;
    size_t base = (size_t)(n0 + nl) * (2 * KP) + k0;
#pragma unroll
    for (int q = 0; q < 4; q++) {
        int kk = kg + q * 2;
        float v0 = t[kk][nl], v1 = t[kk + 1][nl];
        __nv_bfloat16 h0 = __float2bfloat16(v0), h1 = __float2bfloat16(v1);
        __nv_bfloat16 l0 = __float2bfloat16(v0 - __bfloat162float(h0));
        __nv_bfloat16 l1 = __float2bfloat16(v1 - __bfloat162float(h1));
        uint32_t hp = ((uint32_t)__bfloat16_as_ushort(h1) << 16) | __bfloat16_as_ushort(h0);
        uint32_t lp = ((uint32_t)__bfloat16_as_ushort(l1) << 16) | __bfloat16_as_ushort(l0);
        *reinterpret_cast<uint32_t*>(&dst[base + kk]) = hp;
        *reinterpret_cast<uint32_t*>(&dst[base + KP + kk]) = lp;
    }
}

// ---------------- scalar SGEMM (tiny MLP tail layers) ----------------
__global__ __launch_bounds__(256) void sgemm(const float* __restrict__ A,
                                             const float* __restrict__ B,
                                             const float* __restrict__ bias,
                                             float* __restrict__ C,
                                             int M, int N, int K,
                                             int hasBias, int doRelu) {
    __shared__ float As[8][128];
    __shared__ float Bs[8][128];
    const int tid   = threadIdx.x;
    const int tileM = blockIdx.y * 128;
    const int tileN = blockIdx.x * 128;

    const int aRow = tid >> 1;
    const int aK4  = (tid & 1) * 4;
    const int bRow = tid >> 5;
    const int bCol = (tid & 31) * 4;
    const int ty   = tid >> 4;
    const int tx   = tid & 15;

    float acc[8][8];
#pragma unroll
    for (int i = 0; i < 8; i++)
#pragma unroll
        for (int j = 0; j < 8; j++) acc[i][j] = 0.f;

    for (int k0 = 0; k0 < K; k0 += 8) {
        float4 av = make_float4(0.f, 0.f, 0.f, 0.f);
        int gr = tileM + aRow;
        if (gr < M) av = *reinterpret_cast<const float4*>(&A[(size_t)gr * K + k0 + aK4]);
        As[aK4 + 0][aRow] = av.x;
        As[aK4 + 1][aRow] = av.y;
        As[aK4 + 2][aRow] = av.z;
        As[aK4 + 3][aRow] = av.w;

        float4 bv = make_float4(0.f, 0.f, 0.f, 0.f);
        int gc = tileN + bCol;
        const float* bp = &B[(size_t)(k0 + bRow) * N + gc];
        if (gc + 3 < N) {
            bv = *reinterpret_cast<const float4*>(bp);
        } else {
            if (gc + 0 < N) bv.x = bp[0];
            if (gc + 1 < N) bv.y = bp[1];
            if (gc + 2 < N) bv.z = bp[2];
            if (gc + 3 < N) bv.w = bp[3];
        }
        *reinterpret_cast<float4*>(&Bs[bRow][bCol]) = bv;

        __syncthreads();
#pragma unroll
        for (int kk = 0; kk < 8; kk++) {
            float a[8], b[8];
            *reinterpret_cast<float4*>(&a[0]) = *reinterpret_cast<float4*>(&As[kk][ty * 8]);
            *reinterpret_cast<float4*>(&a[4]) = *reinterpret_cast<float4*>(&As[kk][ty * 8 + 4]);
            *reinterpret_cast<float4*>(&b[0]) = *reinterpret_cast<float4*>(&Bs[kk][tx * 8]);
            *reinterpret_cast<float4*>(&b[4]) = *reinterpret_cast<float4*>(&Bs[kk][tx * 8 + 4]);
#pragma unroll
            for (int i = 0; i < 8; i++)
#pragma unroll
                for (int j = 0; j < 8; j++) acc[i][j] = fmaf(a[i], b[j], acc[i][j]);
        }
        __syncthreads();
    }

#pragma unroll
    for (int i = 0; i < 8; i++) {
        int row = tileM + ty * 8 + i;
        if (row >= M) continue;
#pragma unroll
        for (int j = 0; j < 8; j++) {
            int col = tileN + tx * 8 + j;
            if (col < N) {
                float v = acc[i][j];
                if (hasBias) v += bias[col];
                if (doRelu) v = fmaxf(v, 0.f);
                C[(size_t)row * N + col] = v;
            }
        }
    }
}

// ---------------- CSR build ----------------
__global__ void k_init() {
    int i = blockIdx.x * blockDim.x + threadIdx.x;
    if (i < NN) { g_cnt[i] = 0; g_cur[i] = 0; }
    if (i < GG) { g_pstart[i] = 0x7fffffff; g_pend[i] = -1; g_pcnt[i] = 0; }
}

__global__ void k_count(const int* __restrict__ ei) {
    int k = blockIdx.x * blockDim.x + threadIdx.x;
    if (k >= ETOT) return;
    int dst = (k < EE) ? ei[EE + k] : (k - EE);
    atomicAdd(&g_cnt[dst], 1);
}

__global__ __launch_bounds__(1024) void k_scan() {
    __shared__ int sd[1024];
    __shared__ int scarry;
    int tid = threadIdx.x;
    if (tid == 0) { scarry = 0; g_start[0] = 0; }
    __syncthreads();
    for (int base = 0; base < NN; base += 1024) {
        int v = (base + tid < NN) ? g_cnt[base + tid] : 0;
        sd[tid] = v;
        __syncthreads();
        for (int o = 1; o < 1024; o <<= 1) {
            int t = (tid >= o) ? sd[tid - o] : 0;
            __syncthreads();
            sd[tid] += t;
            __syncthreads();
        }
        int run = scarry;
        if (base + tid < NN) g_start[base + tid + 1] = run + sd[tid];
        __syncthreads();
        if (tid == 1023) scarry = run + sd[1023];
        __syncthreads();
    }
}

__global__ void k_scatter(const int* __restrict__ ei) {
    int k = blockIdx.x * blockDim.x + threadIdx.x;
    if (k >= ETOT) return;
    int src = (k < EE) ? ei[k]      : (k - EE);
    int dst = (k < EE) ? ei[EE + k] : (k - EE);
    int pos = g_start[dst] + atomicAdd(&g_cur[dst], 1);
    g_esrc[pos] = src;
}

__global__ void k_dinv() {
    int i = blockIdx.x * blockDim.x + threadIdx.x;
    if (i < NN) g_dinv[i] = rsqrtf((float)g_cnt[i]);
}

// ---------------- attention ----------------
__global__ void k_attn(const float* __restrict__ xh, const float* __restrict__ a_s,
                       const float* __restrict__ a_d) {
    int n = blockIdx.x;
    int w = threadIdx.x >> 5;
    int lane = threadIdx.x & 31;
    if (w >= HH) return;
    const float* row = xh + (size_t)n * HFD + w * FF;
    const float* as  = a_s + w * FF;
    const float* ad  = a_d + w * FF;
    float s1 = 0.f, s2 = 0.f;
    for (int f = lane; f < FF; f += 32) {
        float v = row[f];
        s1 = fmaf(v, as[f], s1);
        s2 = fmaf(v, ad[f], s2);
    }
#pragma unroll
    for (int o = 16; o; o >>= 1) {
        s1 += __shfl_down_sync(0xffffffffu, s1, o);
        s2 += __shfl_down_sync(0xffffffffu, s2, o);
    }
    if (lane == 0) { g_als[n * HH + w] = s1; g_ald[n * HH + w] = s2; }
}

__global__ void k_softmax() {
    int node = blockIdx.x * blockDim.y + threadIdx.y;
    if (node >= NN) return;
    int lane = threadIdx.x;
    bool act = lane < HH;
    int s = g_start[node], e = g_start[node + 1];
    float ald_v = act ? g_ald[node * HH + lane] : 0.f;
    float mx = -3.0e38f;
    for (int p = s; p < e; p++) {
        int src = g_esrc[p];
        if (act) {
            float v = g_als[src * HH + lane] + ald_v;
            v = fmaxf(v, 0.2f * v);
            mx = fmaxf(mx, v);
        }
    }
    float z = 0.f;
    for (int p = s; p < e; p++) {
        int src = g_esrc[p];
        if (act) {
            float v = g_als[src * HH + lane] + ald_v;
            v = fmaxf(v, 0.2f * v);
            float ex = expf(v - mx);
            g_alpha[(size_t)p * HH + lane] = ex;
            z += ex;
        }
    }
    float inv = 1.f / (z + 1e-16f);
    for (int p = s; p < e; p++)
        if (act) g_alpha[(size_t)p * HH + lane] *= inv;
}

// ---------------- GAT aggregation fused with A-panel split (grid = MP_G) ----------------
__global__ __launch_bounds__(256) void k_gat_agg_split(const float* __restrict__ bias) {
    int n = blockIdx.x, tid = threadIdx.x;
    __nv_bfloat16* arow = s_a2 + (size_t)n * (2 * KP2);
    if (n >= NN) {
        for (int k = tid; k < 2 * KP2 / 2; k += 256)
            reinterpret_cast<uint32_t*>(arow)[k] = 0;
        return;
    }
    int s = g_start[n], e = g_start[n + 1];
    float2 acc[PCH];
    int hidx[PCH];
#pragma unroll
    for (int i = 0; i < PCH; i++) {
        int f = 2 * tid + 512 * i;
        hidx[i] = (f < HFD) ? (f / FF) : 0;
        acc[i].x = (f < HFD) ? bias[f] : 0.f;
        acc[i].y = (f + 1 < HFD) ? bias[f + 1] : 0.f;
    }
    for (int p = s; p < e; p++) {
        int src = g_esrc[p];
        const float2* xr = reinterpret_cast<const float2*>(g_xh + (size_t)src * HFD);
        const float* al = g_alpha + (size_t)p * HH;
#pragma unroll
        for (int i = 0; i < PCH; i++) {
            int f = 2 * tid + 512 * i;
            if (f < HFD) {
                float2 v = xr[f >> 1];
                float a = al[hidx[i]];
                acc[i].x = fmaf(a, v.x, acc[i].x);
                acc[i].y = fmaf(a, v.y, acc[i].y);
            }
        }
    }
#pragma unroll
    for (int i = 0; i < PCH; i++) {
        int f = 2 * tid + 512 * i;
        if (f < KP2) {
            float vx = (f < HFD) ? fmaxf(acc[i].x, 0.f) : 0.f;
            float vy = (f + 1 < HFD) ? fmaxf(acc[i].y, 0.f) : 0.f;
            __nv_bfloat16 hx = __float2bfloat16(vx), hy = __float2bfloat16(vy);
            __nv_bfloat16 lx = __float2bfloat16(vx - __bfloat162float(hx));
            __nv_bfloat16 ly = __float2bfloat16(vy - __bfloat162float(hy));
            uint32_t hp = ((uint32_t)__bfloat16_as_ushort(hy) << 16) | __bfloat16_as_ushort(hx);
            uint32_t lp = ((uint32_t)__bfloat16_as_ushort(ly) << 16) | __bfloat16_as_ushort(lx);
            *reinterpret_cast<uint32_t*>(&arow[f]) = hp;
            *reinterpret_cast<uint32_t*>(&arow[KP2 + f]) = lp;
        }
    }
}

// ---------------- GCN aggregation (fp32 out, bias+relu fused) ----------------
#define FCH 27
__global__ __launch_bounds__(256) void k_gcn_agg(const float* __restrict__ bias) {
    int n = blockIdx.x, tid = threadIdx.x;
    int s = g_start[n], e = g_start[n + 1];
    float dv = g_dinv[n];
    float acc[FCH];
#pragma unroll
    for (int i = 0; i < FCH; i++) {
        int f = tid + i * 256;
        acc[i] = (f < HFD) ? bias[f] : 0.f;
    }
    for (int p = s; p < e; p++) {
        int src = g_esrc[p];
        float coef = g_dinv[src] * dv;
        const float* xr = g_xw + (size_t)src * HFD;
#pragma unroll
        for (int i = 0; i < FCH; i++) {
            int f = tid + i * 256;
            if (f < HFD) acc[i] = fmaf(coef, xr[f], acc[i]);
        }
    }
    float* o = g_h2 + (size_t)n * HFD;
#pragma unroll
    for (int i = 0; i < FCH; i++) {
        int f = tid + i * 256;
        if (f < HFD) o[f] = fmaxf(acc[i], 0.f);
    }
}

// ---------------- pooling fused with MLP1 A-panel split ----------------
__global__ void k_ranges(const int* __restrict__ batch) {
    int i = blockIdx.x * blockDim.x + threadIdx.x;
    if (i >= NN) return;
    int b = batch[i];
    if (b >= 0 && b < GG) {
        atomicMin(&g_pstart[b], i);
        atomicMax(&g_pend[b], i);
        atomicAdd(&g_pcnt[b], 1);
    }
}

__device__ __forceinline__ void bf_split_store(__nv_bfloat16* hi, __nv_bfloat16* lo, float v) {
    __nv_bfloat16 h = __float2bfloat16(v);
    *hi = h;
    *lo = __float2bfloat16(v - __bfloat162float(h));
}

__global__ __launch_bounds__(256) void k_pool_split() {
    int g = blockIdx.y;
    int f = blockIdx.x * blockDim.x + threadIdx.x;
    if (f >= HFD) return;
    int s = g_pstart[g], e = g_pend[g];
    float mx = -3.0e38f, sm = 0.f;
    for (int n = s; n <= e; n++) {
        float v = g_h2[(size_t)n * HFD + f];
        mx = fmaxf(mx, v);
        sm += v;
    }
    float gap = sm / (float)g_pcnt[g];
    __nv_bfloat16* row = s_a2 + (size_t)g * (2 * KPM);
    bf_split_store(&row[f],       &row[KPM + f],       mx);
    bf_split_store(&row[HFD + f], &row[KPM + HFD + f], gap);
}

__global__ void k_pool_pad() {
    int g = blockIdx.x;
    int t = threadIdx.x;
    __nv_bfloat16* row = s_a2 + (size_t)g * (2 * KPM);
    row[HF2 + t] = __float2bfloat16(0.f);
    row[KPM + HF2 + t] = __float2bfloat16(0.f);
}

// ---------------- launch ----------------
extern "C" void kernel_launch(void* const* d_in, const int* in_sizes, int n_in,
                              void* d_out, int out_size) {
    const float* x     = (const float*)d_in[0];
    const int*   ei    = (const int*)  d_in[1];
    const int*   batch = (const int*)  d_in[2];
    const float* W_gat = (const float*)d_in[3];
    const float* a_src = (const float*)d_in[4];
    const float* a_dst = (const float*)d_in[5];
    const float* b_gat = (const float*)d_in[6];
    const float* W_gcn = (const float*)d_in[7];
    const float* b_gcn = (const float*)d_in[8];
    const float* W1    = (const float*)d_in[9];
    const float* b1    = (const float*)d_in[10];
    const float* W2    = (const float*)d_in[11];
    const float* b2    = (const float*)d_in[12];
    const float* W3    = (const float*)d_in[13];
    const float* b3    = (const float*)d_in[14];
    float* out = (float*)d_out;

    float *p_xh, *p_xw, *p_m1, *p_m2;
    __nv_bfloat16 *p_a2, *p_b2;
    cudaGetSymbolAddress((void**)&p_xh,   g_xh);
    cudaGetSymbolAddress((void**)&p_xw,   g_xw);
    cudaGetSymbolAddress((void**)&p_m1,   g_mlp1);
    cudaGetSymbolAddress((void**)&p_m2,   g_mlp2);
    cudaGetSymbolAddress((void**)&p_a2,   s_a2);
    cudaGetSymbolAddress((void**)&p_b2,   s_b2);

    cudaFuncSetAttribute(mma_gemm, cudaFuncAttributeMaxDynamicSharedMemorySize, SMEM_MMA);

    const int TM = MP_G / 128;   // 63
    const int TN = NPAD / 128;   // 54

    // ---- GEMM1 split first; mma_gemm lands at launch index 3 (ncu capture slot) ----
    {
        dim3 gA((KP1 / 4 + 255) / 256, MP_G);
        k_splitA2<<<gA, 256>>>(x, p_a2, NN, FF, KP1);                 // 0
        dim3 gB(KP1 / 64, NPAD / 32);
        k_splitBT2<<<gB, dim3(32, 8)>>>(W_gat, p_b2, FF, HFD, KP1);   // 1
    }
    k_init<<<(NN + 255) / 256, 256>>>();                               // 2
    mma_gemm<<<TM * TN, 256, SMEM_MMA>>>(p_a2, p_b2, nullptr, p_xh,    // 3 <- profiled
                                         NN, HFD, HFD, KP1, TM, TN, 0);

    // CSR build + degrees
    k_count<<<(ETOT + 255) / 256, 256>>>(ei);
    k_scan<<<1, 1024>>>();
    k_scatter<<<(ETOT + 255) / 256, 256>>>(ei);
    k_dinv<<<(NN + 255) / 256, 256>>>();

    k_attn<<<NN, 320>>>(p_xh, a_src, a_dst);
    k_softmax<<<(NN + 7) / 8, dim3(32, 8)>>>();
    k_gat_agg_split<<<MP_G, 256>>>(b_gat);

    // ---- GEMM2: xw = h @ W_gcn ----
    {
        dim3 gB(KP2 / 64, NPAD / 32);
        k_splitBT2<<<gB, dim3(32, 8)>>>(W_gcn, p_b2, HFD, HFD, KP2);
        mma_gemm<<<TM * TN, 256, SMEM_MMA>>>(p_a2, p_b2, nullptr, p_xw,
                                             NN, HFD, HFD, KP2, TM, TN, 0);
    }

    k_gcn_agg<<<NN, 256>>>(b_gcn);

    // pooling (writes MLP1 A-panel directly)
    k_ranges<<<(NN + 255) / 256, 256>>>(batch);
    {
        dim3 grid((HFD + 255) / 256, GG);
        k_pool_split<<<grid, 256>>>();
        k_pool_pad<<<GG, 32>>>();
    }

    // ---- MLP1: relu(pool @ W1 + b1) ----
    {
        dim3 gB(KPM / 64, 512 / 32);
        k_splitBT2<<<gB, dim3(32, 8)>>>(W1, p_b2, HF2, 512, KPM);
        mma_gemm<<<2 * 4, 256, SMEM_MMA>>>(p_a2, p_b2, b1, p_m1,
                                           GG, 512, 512, KPM, 2, 4, 3);
    }

    // MLP tail (tiny)
    {
        dim3 grid(1, 2);
        sgemm<<<grid, 256>>>(p_m1, W2, b2, p_m2, GG, 128, 512, 1, 0);
    }
    {
        dim3 grid(1, 2);
        sgemm<<<grid, 256>>>(p_m2, W3, b3, out, GG, 64, 128, 1, 0);
    }
}